// round 1
// baseline (speedup 1.0000x reference)
#include <cuda_runtime.h>

// FFTConv2d_88819923681993
// Reference == direct cross-correlation: out[b,o,y,x] =
//   sum_{c,i,j} signal[b,c,y+i-15,x+j-15] * w[o,c,i,j] + bias[o]
// (286-pt circular correlation never wraps into the kept 256x256 region)
//
// Round 1: packed-f32x2 direct conv. One CTA per (b, y): 256 px x 64 oc.
// Inner loop is FFMA2 (fma.rn.f32x2) with duplicated-input smem so no packs.

namespace fc {
constexpr int Bn = 8;
constexpr int C  = 64;
constexpr int OC = 64;
constexpr int H  = 256;
constexpr int W  = 256;
constexpr int K  = 31;
constexpr int PD = 15;
constexpr int NROW   = W + 2 * PD;  // 286 staged input columns
constexpr int WPITCH = 66;          // padded weight pitch: even (8B-aligned pairs),
                                    // 66 mod 32 spreads STS banks (<=2-way)
}

__device__ __forceinline__ unsigned long long ffma2(unsigned long long a,
                                                    unsigned long long b,
                                                    unsigned long long c) {
    unsigned long long d;
    asm("fma.rn.f32x2 %0, %1, %2, %3;" : "=l"(d) : "l"(a), "l"(b), "l"(c));
    return d;
}

__device__ __forceinline__ unsigned long long pack2(float x, float y) {
    unsigned long long r;
    asm("mov.b64 %0, {%1, %2};" : "=l"(r) : "f"(x), "f"(y));
    return r;
}

__global__ void __launch_bounds__(256, 2)
fftconv_direct_kernel(const float* __restrict__ sig,
                      const float* __restrict__ wgt,
                      const float* __restrict__ bias,
                      float* __restrict__ out)
{
    using namespace fc;
    __shared__ __align__(16) float ws[K * WPITCH];          // [j][oc], 8184 B
    __shared__ unsigned long long ind[NROW];                // {v,v} dup row, 2288 B

    const int tid  = threadIdx.x;
    const int tcol = tid & 31;   // px group: thread covers px = tcol + 32*p
    const int trow = tid >> 5;   // oc group: thread covers oc = trow*8 + 2k (+1)
    const int y    = blockIdx.x;
    const int b    = blockIdx.y;

    unsigned long long acc[4][8];
#pragma unroll
    for (int k = 0; k < 4; ++k)
#pragma unroll
        for (int p = 0; p < 8; ++p) acc[k][p] = 0ULL;  // {+0.f, +0.f}

    const float* sb = sig + (size_t)b * C * H * W;

    for (int c = 0; c < C; ++c) {
        const float* srow0 = sb + (size_t)c * H * W;
        for (int i = 0; i < K; ++i) {
            __syncthreads();  // protect smem from previous iteration's readers

            // ---- stage one padded input row, duplicated to {v,v} ----
            const int yy    = y + i - PD;            // [-15, 270]
            const bool rowok = ((unsigned)yy < (unsigned)H);
            {
                const int xx = tid - PD;
                float v = 0.f;
                if (rowok && (unsigned)xx < (unsigned)W) v = srow0[yy * W + xx];
                ind[tid] = pack2(v, v);
                if (tid < NROW - 256) {
                    const int q  = 256 + tid;
                    const int x2 = q - PD;           // 241..255+
                    float v2 = 0.f;
                    if (rowok && x2 < W) v2 = srow0[yy * W + x2];
                    ind[q] = pack2(v2, v2);
                }
            }

            // ---- stage weight slice w[0:64, c, i, 0:31] transposed -> ws[j][oc] ----
            for (int idx = tid; idx < OC * K; idx += 256) {
                const int oc = idx / K;
                const int j  = idx - oc * K;
                ws[j * WPITCH + oc] = wgt[(((size_t)oc * C + c) * K + i) * K + j];
            }
            __syncthreads();

            // ---- accumulate: per thread 64 MAC per j via 32 FFMA2 ----
            const float* wsr = ws + trow * 8;
#pragma unroll 1
            for (int j = 0; j < K; ++j) {
                const float* wj = wsr + j * WPITCH;
                const unsigned long long w0 = *(const unsigned long long*)(wj + 0);
                const unsigned long long w1 = *(const unsigned long long*)(wj + 2);
                const unsigned long long w2 = *(const unsigned long long*)(wj + 4);
                const unsigned long long w3 = *(const unsigned long long*)(wj + 6);
                const unsigned long long* iv0 = ind + tcol + j;
#pragma unroll
                for (int p = 0; p < 8; ++p) {
                    const unsigned long long iv = iv0[32 * p];
                    acc[0][p] = ffma2(iv, w0, acc[0][p]);
                    acc[1][p] = ffma2(iv, w1, acc[1][p]);
                    acc[2][p] = ffma2(iv, w2, acc[2][p]);
                    acc[3][p] = ffma2(iv, w3, acc[3][p]);
                }
            }
        }
    }

    // ---- epilogue: add bias, store coalesced (lanes = consecutive px) ----
#pragma unroll
    for (int k = 0; k < 4; ++k) {
        const int oc = trow * 8 + 2 * k;
        const float b0 = bias[oc];
        const float b1 = bias[oc + 1];
        float* o0 = out + (((size_t)b * OC + oc) * H + y) * W;
        float* o1 = o0 + (size_t)H * W;
#pragma unroll
        for (int p = 0; p < 8; ++p) {
            const unsigned long long a = acc[k][p];
            const float lo = __uint_as_float((unsigned)(a & 0xffffffffULL));
            const float hi = __uint_as_float((unsigned)(a >> 32));
            const int px = tcol + 32 * p;
            o0[px] = lo + b0;
            o1[px] = hi + b1;
        }
    }
}

extern "C" void kernel_launch(void* const* d_in, const int* in_sizes, int n_in,
                              void* d_out, int out_size)
{
    using namespace fc;
    const float* sig  = (const float*)d_in[0];  // (8, 64, 256, 256)
    const float* wgt  = (const float*)d_in[1];  // (64, 64, 31, 31)
    const float* bias = (const float*)d_in[2];  // (64,)
    float* out = (float*)d_out;                 // (8, 64, 256, 256) fp32

    dim3 grid(H, Bn);   // one CTA per (output row, batch)
    fftconv_direct_kernel<<<grid, 256>>>(sig, wgt, bias, out);
}

// round 3
// speedup vs baseline: 1.0549x; 1.0549x over previous
#include <cuda_runtime.h>

// FFTConv2d_88819923681993
// Reference == direct cross-correlation: out[b,o,y,x] =
//   sum_{c,i,j} signal[b,c,y+i-15,x+j-15] * w[o,c,i,j] + bias[o]
// (286-pt circular correlation never wraps into the kept 256x256 region)
//
// Round 1: packed-f32x2 direct conv. One CTA per (b, y): 256 px x 64 oc.
// Inner loop is FFMA2 (fma.rn.f32x2) with duplicated-input smem so no packs.

namespace fc {
constexpr int Bn = 8;
constexpr int C  = 64;
constexpr int OC = 64;
constexpr int H  = 256;
constexpr int W  = 256;
constexpr int K  = 31;
constexpr int PD = 15;
constexpr int NROW   = W + 2 * PD;  // 286 staged input columns
constexpr int WPITCH = 66;          // padded weight pitch: even (8B-aligned pairs),
                                    // 66 mod 32 spreads STS banks (<=2-way)
}

__device__ __forceinline__ unsigned long long ffma2(unsigned long long a,
                                                    unsigned long long b,
                                                    unsigned long long c) {
    unsigned long long d;
    asm("fma.rn.f32x2 %0, %1, %2, %3;" : "=l"(d) : "l"(a), "l"(b), "l"(c));
    return d;
}

__device__ __forceinline__ unsigned long long pack2(float x, float y) {
    unsigned long long r;
    asm("mov.b64 %0, {%1, %2};" : "=l"(r) : "f"(x), "f"(y));
    return r;
}

__global__ void __launch_bounds__(256, 2)
fftconv_direct_kernel(const float* __restrict__ sig,
                      const float* __restrict__ wgt,
                      const float* __restrict__ bias,
                      float* __restrict__ out)
{
    using namespace fc;
    __shared__ __align__(16) float ws[K * WPITCH];          // [j][oc], 8184 B
    __shared__ unsigned long long ind[NROW];                // {v,v} dup row, 2288 B

    const int tid  = threadIdx.x;
    const int tcol = tid & 31;   // px group: thread covers px = tcol + 32*p
    const int trow = tid >> 5;   // oc group: thread covers oc = trow*8 + 2k (+1)
    const int y    = blockIdx.x;
    const int b    = blockIdx.y;

    unsigned long long acc[4][8];
#pragma unroll
    for (int k = 0; k < 4; ++k)
#pragma unroll
        for (int p = 0; p < 8; ++p) acc[k][p] = 0ULL;  // {+0.f, +0.f}

    const float* sb = sig + (size_t)b * C * H * W;

    for (int c = 0; c < C; ++c) {
        const float* srow0 = sb + (size_t)c * H * W;
        for (int i = 0; i < K; ++i) {
            __syncthreads();  // protect smem from previous iteration's readers

            // ---- stage one padded input row, duplicated to {v,v} ----
            const int yy    = y + i - PD;            // [-15, 270]
            const bool rowok = ((unsigned)yy < (unsigned)H);
            {
                const int xx = tid - PD;
                float v = 0.f;
                if (rowok && (unsigned)xx < (unsigned)W) v = srow0[yy * W + xx];
                ind[tid] = pack2(v, v);
                if (tid < NROW - 256) {
                    const int q  = 256 + tid;
                    const int x2 = q - PD;           // 241..255+
                    float v2 = 0.f;
                    if (rowok && x2 < W) v2 = srow0[yy * W + x2];
                    ind[q] = pack2(v2, v2);
                }
            }

            // ---- stage weight slice w[0:64, c, i, 0:31] transposed -> ws[j][oc] ----
            for (int idx = tid; idx < OC * K; idx += 256) {
                const int oc = idx / K;
                const int j  = idx - oc * K;
                ws[j * WPITCH + oc] = wgt[(((size_t)oc * C + c) * K + i) * K + j];
            }
            __syncthreads();

            // ---- accumulate: per thread 64 MAC per j via 32 FFMA2 ----
            const float* wsr = ws + trow * 8;
#pragma unroll 1
            for (int j = 0; j < K; ++j) {
                const float* wj = wsr + j * WPITCH;
                const unsigned long long w0 = *(const unsigned long long*)(wj + 0);
                const unsigned long long w1 = *(const unsigned long long*)(wj + 2);
                const unsigned long long w2 = *(const unsigned long long*)(wj + 4);
                const unsigned long long w3 = *(const unsigned long long*)(wj + 6);
                const unsigned long long* iv0 = ind + tcol + j;
#pragma unroll
                for (int p = 0; p < 8; ++p) {
                    const unsigned long long iv = iv0[32 * p];
                    acc[0][p] = ffma2(iv, w0, acc[0][p]);
                    acc[1][p] = ffma2(iv, w1, acc[1][p]);
                    acc[2][p] = ffma2(iv, w2, acc[2][p]);
                    acc[3][p] = ffma2(iv, w3, acc[3][p]);
                }
            }
        }
    }

    // ---- epilogue: add bias, store coalesced (lanes = consecutive px) ----
#pragma unroll
    for (int k = 0; k < 4; ++k) {
        const int oc = trow * 8 + 2 * k;
        const float b0 = bias[oc];
        const float b1 = bias[oc + 1];
        float* o0 = out + (((size_t)b * OC + oc) * H + y) * W;
        float* o1 = o0 + (size_t)H * W;
#pragma unroll
        for (int p = 0; p < 8; ++p) {
            const unsigned long long a = acc[k][p];
            const float lo = __uint_as_float((unsigned)(a & 0xffffffffULL));
            const float hi = __uint_as_float((unsigned)(a >> 32));
            const int px = tcol + 32 * p;
            o0[px] = lo + b0;
            o1[px] = hi + b1;
        }
    }
}

extern "C" void kernel_launch(void* const* d_in, const int* in_sizes, int n_in,
                              void* d_out, int out_size)
{
    using namespace fc;
    const float* sig  = (const float*)d_in[0];  // (8, 64, 256, 256)
    const float* wgt  = (const float*)d_in[1];  // (64, 64, 31, 31)
    const float* bias = (const float*)d_in[2];  // (64,)
    float* out = (float*)d_out;                 // (8, 64, 256, 256) fp32

    dim3 grid(H, Bn);   // one CTA per (output row, batch)
    fftconv_direct_kernel<<<grid, 256>>>(sig, wgt, bias, out);
}

// round 5
// speedup vs baseline: 2.9276x; 2.7754x over previous
#include <cuda_runtime.h>
#include <cstdint>

// FFTConv2d == direct cross-correlation:
//   out[b,o,y,x] = sum_{c,i,j} sig[b,c,y+i-15,x+j-15] * w[o,c,i,j] + bias[o]
// Implicit GEMM on warp-level tensor cores (mma.sync tf32, sm_80+ family-safe;
// tcgen05 is rejected by the harness's compute_103 family target).
// CTA = (b, y): D[256px][64oc]. A is Toeplitz (rowbuf), B is bank-swizzled.

namespace fc {
constexpr int Cc = 64, OC = 64, Hh = 256, Ww = 256, Kk = 31, PD = 15;
constexpr int WSP = 160;   // ws row pitch (words); rows indexed by ks*4+cl
}

__device__ __forceinline__ uint32_t to_tf32(float x) {
    uint32_t r;
    asm("cvt.rn.tf32.f32 %0, %1;" : "=r"(r) : "f"(x));
    return r;
}

#define MMA_TF32(acc, av, b0, b1)                                          \
    asm volatile("mma.sync.aligned.m16n8k8.row.col.f32.tf32.tf32.f32 "     \
                 "{%0,%1,%2,%3}, {%4,%5,%6,%7}, {%8,%9}, {%0,%1,%2,%3};"   \
                 : "+f"((acc)[0]), "+f"((acc)[1]),                         \
                   "+f"((acc)[2]), "+f"((acc)[3])                          \
                 : "r"((av)[0]), "r"((av)[1]), "r"((av)[2]), "r"((av)[3]), \
                   "r"(b0), "r"(b1))

__global__ void __launch_bounds__(256, 2)
fftconv_mma_kernel(const float* __restrict__ sig,
                   const float* __restrict__ wgt,
                   const float* __restrict__ bias,
                   float* __restrict__ out)
{
    using namespace fc;
    // rowbuf[q] = tf32(sig[b, c, y+i-15, q-15]) (0 outside), q in [0, 287]
    __shared__ uint32_t rowbuf[288];
    // ws[row=ks*4+cl][col*2+sel], col = oc + 4*(j&3) + (j>>3); j = ks*8+cl+4*sel
    // Verified conflict-free for STS (this mapping) and LDS.64 fragment loads.
    __shared__ uint32_t ws[16 * WSP];

    const int tid  = threadIdx.x;
    const int wid  = tid >> 5;
    const int lane = tid & 31;
    const int r    = lane >> 2;   // fragment row group
    const int cl   = lane & 3;    // fragment col group
    const int y    = blockIdx.x;
    const int b    = blockIdx.y;
    const int wm   = wid * 32;    // warp's 32-px M slice

    float acc[2][8][4];
#pragma unroll
    for (int mt = 0; mt < 2; ++mt)
#pragma unroll
        for (int nt = 0; nt < 8; ++nt)
#pragma unroll
            for (int q = 0; q < 4; ++q) acc[mt][nt][q] = 0.f;

    const float* sbase = sig + (size_t)b * Cc * Hh * Ww;

    // ---- prefetch registers (software pipeline over the (c,i) loop) ----
    uint32_t pfr0, pfr1, pfw[8];
    auto prefetch = [&](int c2, int i2) {
        const int yy = y + i2 - PD;
        const bool rowok = ((unsigned)yy < (unsigned)Hh);
        const float* srow = sbase + ((size_t)c2 * Hh + (rowok ? yy : 0)) * Ww;
        const int x = tid - PD;
        pfr0 = (rowok && (unsigned)x < (unsigned)Ww) ? to_tf32(srow[x]) : 0u;
        pfr1 = 0u;
        if (tid < 32) {
            const int x2 = 241 + tid;                  // (256+tid) - 15
            if (rowok && x2 < Ww) pfr1 = to_tf32(srow[x2]);
        }
        // oc = e*8 + wid, j = lane  (gmem: lanes hit consecutive j -> coalesced)
#pragma unroll
        for (int e = 0; e < 8; ++e) {
            const int oc = e * 8 + wid;
            pfw[e] = (lane < Kk)
                ? to_tf32(wgt[(((size_t)oc * Cc + c2) * Kk + i2) * Kk + lane])
                : 0u;
        }
    };
    prefetch(0, 0);

    for (int c = 0; c < Cc; ++c) {
        for (int i = 0; i < Kk; ++i) {
            __syncthreads();   // previous iteration's readers are done

            // ---- store staged registers to smem ----
            rowbuf[tid] = pfr0;
            if (tid < 32) rowbuf[256 + tid] = pfr1;
            {
                const int j   = lane;                      // 0..31 (31 = pad)
                const int row = ((j >> 3) << 2) | (j & 3); // ks*4 + cl
                const int sel = (j >> 2) & 1;
                const int colb = 4 * (j & 3) + (j >> 3);   // swizzle part
#pragma unroll
                for (int e = 0; e < 8; ++e) {
                    const int oc = e * 8 + wid;
                    ws[row * WSP + (oc + colb) * 2 + sel] = pfw[e];
                }
            }
            __syncthreads();

            // ---- prefetch next (c,i): LDG latency hides under compute ----
            if (!(c == Cc - 1 && i == Kk - 1)) {
                const int i2 = (i == Kk - 1) ? 0 : i + 1;
                const int c2 = (i == Kk - 1) ? c + 1 : c;
                prefetch(c2, i2);
            }

            // ---- compute: 4 k-steps x (2 m-tiles x 8 n-tiles) mma ----
#pragma unroll
            for (int ks = 0; ks < 4; ++ks) {
                uint32_t a[2][4];
#pragma unroll
                for (int mt = 0; mt < 2; ++mt) {
                    const int base = wm + mt * 16 + r + ks * 8 + cl;
                    a[mt][0] = rowbuf[base];
                    a[mt][1] = rowbuf[base + 8];
                    a[mt][2] = rowbuf[base + 4];
                    a[mt][3] = rowbuf[base + 12];
                }
                const int brow = ks * 4 + cl;
#pragma unroll
                for (int nt = 0; nt < 8; ++nt) {
                    const int col = nt * 8 + r + cl * 4 + ks;
                    const uint2 bv =
                        *(const uint2*)&ws[brow * WSP + col * 2];
                    MMA_TF32(acc[0][nt], a[0], bv.x, bv.y);
                    MMA_TF32(acc[1][nt], a[1], bv.x, bv.y);
                }
            }
        }
    }

    // ---- epilogue: d0/d1 -> (px, oc0/oc0+1), d2/d3 -> (px+8, ...) ----
#pragma unroll
    for (int nt = 0; nt < 8; ++nt) {
        const int oc0 = nt * 8 + 2 * cl;
        const float bv0 = bias[oc0];
        const float bv1 = bias[oc0 + 1];
        float* p0 = out + (((size_t)b * OC + oc0) * Hh + y) * Ww;
        float* p1 = p0 + (size_t)Hh * Ww;
#pragma unroll
        for (int mt = 0; mt < 2; ++mt) {
            const int px = wm + mt * 16 + r;
            p0[px]     = acc[mt][nt][0] + bv0;
            p1[px]     = acc[mt][nt][1] + bv1;
            p0[px + 8] = acc[mt][nt][2] + bv0;
            p1[px + 8] = acc[mt][nt][3] + bv1;
        }
    }
}

extern "C" void kernel_launch(void* const* d_in, const int* in_sizes, int n_in,
                              void* d_out, int out_size)
{
    using namespace fc;
    const float* sig  = (const float*)d_in[0];  // (8, 64, 256, 256)
    const float* wgt  = (const float*)d_in[1];  // (64, 64, 31, 31)
    const float* bias = (const float*)d_in[2];  // (64,)
    float* out = (float*)d_out;                 // (8, 64, 256, 256) fp32

    dim3 grid(Hh, 8);   // one CTA per (output row, batch)
    fftconv_mma_kernel<<<grid, 256>>>(sig, wgt, bias, out);
}

// round 6
// speedup vs baseline: 5.9834x; 2.0438x over previous
#include <cuda_runtime.h>
#include <cuda_fp16.h>
#include <cstdint>

// FFTConv2d == direct cross-correlation:
//   out[b,o,y,x] = sum_{c,i,j} sig[b,c,y+i-15,x+j-15] * w[o,c,i,j] + bias[o]
// Implicit GEMM, warp-level mma.sync m16n8k16 fp16 (fp16 mantissa == tf32
// mantissa -> same error stats as the passing tf32 kernel, half the MMAs).
// CTA = (b,y): D[256px][64oc]. A = Toeplitz pair-buffer, B = pitch-20 ws.
// Double-buffered smem, one barrier per (c,i) iteration.

namespace fc {
constexpr int Cc = 64, OC = 64, Hh = 256, Ww = 256, Kk = 31, PD = 15;
constexpr int WSP = 40;     // ws pitch in halves (20 words) -> LDS conflict-free
}

#define MMA16816(d, a, b0v, b1v)                                            \
    asm volatile("mma.sync.aligned.m16n8k16.row.col.f32.f16.f16.f32 "       \
                 "{%0,%1,%2,%3}, {%4,%5,%6,%7}, {%8,%9}, {%0,%1,%2,%3};"    \
                 : "+f"((d)[0]), "+f"((d)[1]), "+f"((d)[2]), "+f"((d)[3])   \
                 : "r"((a)[0]), "r"((a)[1]), "r"((a)[2]), "r"((a)[3]),      \
                   "r"(b0v), "r"(b1v))

__global__ void __launch_bounds__(256, 2)
fftconv_fp16_kernel(const float* __restrict__ sig,
                    const float* __restrict__ wgt,
                    const float* __restrict__ bias,
                    float* __restrict__ out)
{
    using namespace fc;
    // rowp[buf][q] = {half(row[q]), half(row[q+1])}, row[q] = sig val at tap q
    __shared__ __half2 rowp[2][288];
    // ws[buf][oc*WSP + k] (halves, pitch 40); k=31 zero-padded
    __shared__ __half ws[2][64 * WSP];

    const int tid  = threadIdx.x;
    const int wid  = tid >> 5;
    const int lane = tid & 31;
    const int g    = lane >> 2;   // groupID
    const int t4   = lane & 3;    // threadID in group
    const int y    = blockIdx.x;
    const int b    = blockIdx.y;
    const int wm   = wid * 32;    // warp's 32-px M slice

    float acc[2][8][4];
#pragma unroll
    for (int mt = 0; mt < 2; ++mt)
#pragma unroll
        for (int nt = 0; nt < 8; ++nt)
#pragma unroll
            for (int q = 0; q < 4; ++q) acc[mt][nt][q] = 0.f;

    const float* sbase = sig + (size_t)b * Cc * Hh * Ww;

    __half2 pfr0, pfr1;
    __half  pfw[8];
    auto prefetch = [&](int c2, int i2) {
        const int yy = y + i2 - PD;
        const bool rowok = ((unsigned)yy < (unsigned)Hh);
        const float* srow = sbase + ((size_t)c2 * Hh + (rowok ? yy : 0)) * Ww;
        // pair q = tid: values at taps tid, tid+1 (tap q -> x = q-15)
        {
            const int x = tid - PD;
            float f0 = (rowok && (unsigned)x < (unsigned)Ww) ? srow[x] : 0.f;
            float f1 = (rowok && (unsigned)(x + 1) < (unsigned)Ww) ? srow[x + 1] : 0.f;
            pfr0 = __floats2half2_rn(f0, f1);
        }
        if (tid < 32) {
            const int x = 241 + tid;  // tap 256+tid -> x
            float f0 = (rowok && x < Ww) ? srow[x] : 0.f;
            float f1 = (rowok && x + 1 < Ww) ? srow[x + 1] : 0.f;
            pfr1 = __floats2half2_rn(f0, f1);
        }
#pragma unroll
        for (int e = 0; e < 8; ++e) {
            const int oc = e * 8 + wid;
            pfw[e] = (lane < Kk)
                ? __float2half_rn(wgt[(((size_t)oc * Cc + c2) * Kk + i2) * Kk + lane])
                : __half(__ushort_as_half(0));
        }
    };

    prefetch(0, 0);
    // store buf 0
    rowp[0][tid] = pfr0;
    if (tid < 32) rowp[0][256 + tid] = pfr1;
#pragma unroll
    for (int e = 0; e < 8; ++e) ws[0][(e * 8 + wid) * WSP + lane] = pfw[e];
    __syncthreads();

    constexpr int NIT = Cc * Kk;  // 1984
    int c = 0, i = 0;
    for (int t = 0; t < NIT; ++t) {
        const int buf = t & 1;
        const bool more = (t + 1 < NIT);

        // ---- prefetch next (c,i): LDG latency hides under the MMAs ----
        if (more) {
            const int i2 = (i == Kk - 1) ? 0 : i + 1;
            const int c2 = (i == Kk - 1) ? c + 1 : c;
            prefetch(c2, i2);
        }

        // ---- compute from buf: 2 mt x 8 nt x 2 kc m16n8k16 ----
        const uint32_t* rp = (const uint32_t*)rowp[buf];
        const __half*   wb = ws[buf];
#pragma unroll
        for (int mt = 0; mt < 2; ++mt) {
            const int abase = wm + mt * 16 + g + 2 * t4;
            uint32_t p[5];
#pragma unroll
            for (int z = 0; z < 5; ++z) p[z] = rp[abase + 8 * z];
            uint32_t a0[4] = {p[0], p[1], p[1], p[2]};   // kc = 0 (taps 0-15)
            uint32_t a1[4] = {p[2], p[3], p[3], p[4]};   // kc = 1 (taps 16-31)
#pragma unroll
            for (int nt = 0; nt < 8; ++nt) {
                const uint32_t* wrow =
                    (const uint32_t*)(wb + (nt * 8 + g) * WSP) + t4;
                const uint32_t b00 = wrow[0];   // taps 2t..2t+1
                const uint32_t b01 = wrow[4];   // taps 2t+8..2t+9
                const uint32_t b10 = wrow[8];   // taps 16+2t..
                const uint32_t b11 = wrow[12];  // taps 24+2t..
                MMA16816(acc[mt][nt], a0, b00, b01);
                MMA16816(acc[mt][nt], a1, b10, b11);
            }
        }

        // ---- store next buffer (written while nobody reads it) ----
        if (more) {
            const int nb = buf ^ 1;
            rowp[nb][tid] = pfr0;
            if (tid < 32) rowp[nb][256 + tid] = pfr1;
#pragma unroll
            for (int e = 0; e < 8; ++e)
                ws[nb][(e * 8 + wid) * WSP + lane] = pfw[e];
        }
        __syncthreads();

        if (++i == Kk) { i = 0; ++c; }
    }

    // ---- epilogue: c0,c1 -> (px, oc0/oc0+1); c2,c3 -> (px+8, ...) ----
#pragma unroll
    for (int nt = 0; nt < 8; ++nt) {
        const int oc0 = nt * 8 + 2 * t4;
        const float bv0 = bias[oc0];
        const float bv1 = bias[oc0 + 1];
        float* p0 = out + (((size_t)b * OC + oc0) * Hh + y) * Ww;
        float* p1 = p0 + (size_t)Hh * Ww;
#pragma unroll
        for (int mt = 0; mt < 2; ++mt) {
            const int px = wm + mt * 16 + g;
            p0[px]     = acc[mt][nt][0] + bv0;
            p1[px]     = acc[mt][nt][1] + bv1;
            p0[px + 8] = acc[mt][nt][2] + bv0;
            p1[px + 8] = acc[mt][nt][3] + bv1;
        }
    }
}

extern "C" void kernel_launch(void* const* d_in, const int* in_sizes, int n_in,
                              void* d_out, int out_size)
{
    using namespace fc;
    const float* sig  = (const float*)d_in[0];  // (8, 64, 256, 256)
    const float* wgt  = (const float*)d_in[1];  // (64, 64, 31, 31)
    const float* bias = (const float*)d_in[2];  // (64,)
    float* out = (float*)d_out;                 // (8, 64, 256, 256) fp32

    dim3 grid(Hh, 8);   // one CTA per (output row, batch)
    fftconv_fp16_kernel<<<grid, 256>>>(sig, wgt, bias, out);
}

// round 7
// speedup vs baseline: 6.3283x; 1.0576x over previous
#include <cuda_runtime.h>
#include <cuda_fp16.h>
#include <cstdint>

// FFTConv2d == direct cross-correlation:
//   out[b,o,y,x] = sum_{c,i,j} sig[b,c,y+i-15,x+j-15] * w[o,c,i,j] + bias[o]
// Implicit GEMM, mma.sync m16n8k16 fp16. CTA = (b, y0..y0+1): each staged
// input row (c,yy) feeds BOTH output rows (i = s and s-1), halving staging
// work per output. 16 warps: 0-7 -> row y0, 8-15 -> row y0+1.
// B ring of 4 slots (each w[:,c,i] slice read in 2 consecutive iterations).

namespace fc {
constexpr int Cc = 64, OC = 64, Hh = 256, Ww = 256, Kk = 31, PD = 15;
constexpr int WSP = 40;     // ws pitch in halves (20 words) -> LDS conflict-free
constexpr int NIT = Cc * 32;  // 2048 global iterations (s in [0,32))
}

#define MMA16816(d, a, b0v, b1v)                                            \
    asm volatile("mma.sync.aligned.m16n8k16.row.col.f32.f16.f16.f32 "       \
                 "{%0,%1,%2,%3}, {%4,%5,%6,%7}, {%8,%9}, {%0,%1,%2,%3};"    \
                 : "+f"((d)[0]), "+f"((d)[1]), "+f"((d)[2]), "+f"((d)[3])   \
                 : "r"((a)[0]), "r"((a)[1]), "r"((a)[2]), "r"((a)[3]),      \
                   "r"(b0v), "r"(b1v))

__global__ void __launch_bounds__(512, 1)
fftconv_fp16x2_kernel(const float* __restrict__ sig,
                      const float* __restrict__ wgt,
                      const float* __restrict__ bias,
                      float* __restrict__ out)
{
    using namespace fc;
    __shared__ __half2 rowp[2][288];       // pair-buffer: {row[q], row[q+1]}
    __shared__ __half  ws[4][64 * WSP];    // B ring: w[:,c,i] slices

    const int tid  = threadIdx.x;
    const int wid  = tid >> 5;
    const int lane = tid & 31;
    const int g    = lane >> 2;
    const int t4   = lane & 3;
    const int r    = wid >> 3;         // row group: 0 -> y0, 1 -> y0+1
    const int wm   = (wid & 7) * 32;   // warp's 32-px M slice
    const int y0   = blockIdx.x * 2;
    const int b    = blockIdx.y;

    float acc[2][8][4];
#pragma unroll
    for (int mt = 0; mt < 2; ++mt)
#pragma unroll
        for (int nt = 0; nt < 8; ++nt)
#pragma unroll
            for (int q = 0; q < 4; ++q) acc[mt][nt][q] = 0.f;

    const float* sbase = sig + (size_t)b * Cc * Hh * Ww;

    // strength-reduced weight pointers: oc = e*16 + wid, advance +31/slice
    const float* wp[4];
#pragma unroll
    for (int e = 0; e < 4; ++e)
        wp[e] = wgt + (size_t)(e * 16 + wid) * (Cc * Kk * Kk) + lane;
    const bool wlane = (lane < Kk);

    __half2 pfr;
    __half  pfw[4];
    // prefetch for global iter t2 = c2*32 + s2
    auto prefetch = [&](int c2, int s2) {
        const int yy = y0 + s2 - PD;               // input row
        const bool rowok = ((unsigned)yy < (unsigned)Hh);
        const float* srow = sbase + ((size_t)c2 * Hh + (rowok ? yy : 0)) * Ww;
        if (tid < 288) {
            const int x = tid - PD;
            float f0 = (rowok && (unsigned)x < (unsigned)Ww) ? srow[x] : 0.f;
            float f1 = (rowok && (unsigned)(x + 1) < (unsigned)Ww) ? srow[x + 1] : 0.f;
            pfr = __floats2half2_rn(f0, f1);
        }
        if (s2 < Kk) {   // B slice for i = s2
#pragma unroll
            for (int e = 0; e < 4; ++e)
                pfw[e] = wlane ? __float2half_rn(wp[e][0])
                               : __half(__ushort_as_half(0));
        }
    };

    // ---- prologue: stage iter 0 (row s=0, B[i=0]) ----
    prefetch(0, 0);
    if (tid < 288) rowp[0][tid] = pfr;
#pragma unroll
    for (int e = 0; e < 4; ++e) ws[0][(e * 16 + wid) * WSP + lane] = pfw[e];
#pragma unroll
    for (int e = 0; e < 4; ++e) wp[e] += Kk;   // consumed slice (c=0,i=0)
    __syncthreads();

    for (int t = 0; t < NIT; ++t) {
        const int s = t & 31;
        const bool more = (t + 1 < NIT);
        const int ns = (t + 1) & 31;
        const int nc = (t + 1) >> 5;

        // ---- prefetch next iteration (hides LDG under MMAs) ----
        if (more) prefetch(nc, ns);

        // ---- compute ----
        // group 0 (row y0):   i = s,   B slot = t & 3      (valid s < 31)
        // group 1 (row y0+1): i = s-1, B slot = (t-1) & 3  (valid s >= 1)
        const bool valid = r ? (s >= 1) : (s < Kk);
        if (valid) {
            const int slot = r ? ((t + 3) & 3) : (t & 3);
            const uint32_t* rp = (const uint32_t*)rowp[t & 1];
            const __half*   wb = ws[slot];
#pragma unroll
            for (int mt = 0; mt < 2; ++mt) {
                const int abase = wm + mt * 16 + g + 2 * t4;
                uint32_t p[5];
#pragma unroll
                for (int z = 0; z < 5; ++z) p[z] = rp[abase + 8 * z];
                uint32_t a0[4] = {p[0], p[1], p[1], p[2]};   // taps 0-15
                uint32_t a1[4] = {p[2], p[3], p[3], p[4]};   // taps 16-31
#pragma unroll
                for (int nt = 0; nt < 8; ++nt) {
                    const uint32_t* wrow =
                        (const uint32_t*)(wb + (nt * 8 + g) * WSP) + t4;
                    const uint32_t b00 = wrow[0];
                    const uint32_t b01 = wrow[4];
                    const uint32_t b10 = wrow[8];
                    const uint32_t b11 = wrow[12];
                    MMA16816(acc[mt][nt], a0, b00, b01);
                    MMA16816(acc[mt][nt], a1, b10, b11);
                }
            }
        }

        // ---- store next buffers (nobody reads them this iteration) ----
        if (more) {
            if (tid < 288) rowp[(t + 1) & 1][tid] = pfr;
            if (ns < Kk) {
                __half* wd = ws[(t + 1) & 3];
#pragma unroll
                for (int e = 0; e < 4; ++e)
                    wd[(e * 16 + wid) * WSP + lane] = pfw[e];
#pragma unroll
                for (int e = 0; e < 4; ++e) wp[e] += Kk;
            }
        }
        __syncthreads();
    }

    // ---- epilogue ----
    const int yrow = y0 + r;
#pragma unroll
    for (int nt = 0; nt < 8; ++nt) {
        const int oc0 = nt * 8 + 2 * t4;
        const float bv0 = bias[oc0];
        const float bv1 = bias[oc0 + 1];
        float* p0 = out + (((size_t)b * OC + oc0) * Hh + yrow) * Ww;
        float* p1 = p0 + (size_t)Hh * Ww;
#pragma unroll
        for (int mt = 0; mt < 2; ++mt) {
            const int px = wm + mt * 16 + g;
            p0[px]     = acc[mt][nt][0] + bv0;
            p1[px]     = acc[mt][nt][1] + bv1;
            p0[px + 8] = acc[mt][nt][2] + bv0;
            p1[px + 8] = acc[mt][nt][3] + bv1;
        }
    }
}

extern "C" void kernel_launch(void* const* d_in, const int* in_sizes, int n_in,
                              void* d_out, int out_size)
{
    using namespace fc;
    const float* sig  = (const float*)d_in[0];  // (8, 64, 256, 256)
    const float* wgt  = (const float*)d_in[1];  // (64, 64, 31, 31)
    const float* bias = (const float*)d_in[2];  // (64,)
    float* out = (float*)d_out;                 // (8, 64, 256, 256) fp32

    dim3 grid(Hh / 2, 8);   // one CTA per (2 output rows, batch)
    fftconv_fp16x2_kernel<<<grid, 512>>>(sig, wgt, bias, out);
}

// round 9
// speedup vs baseline: 8.1676x; 1.2907x over previous
#include <cuda_runtime.h>
#include <cuda_fp16.h>
#include <cstdint>

// FFTConv2d == direct cross-correlation:
//   out[b,o,y,x] = sum_{c,i,j} sig[b,c,y+i-15,x+j-15] * w[o,c,i,j] + bias[o]
// Implicit GEMM, mma.sync m16n8k16 fp16. CTA = (b, y0..y0+1), 16 warps:
// warps 0-7 accumulate row y0 (i=s), warps 8-15 row y0+1 (i=s-1).
// R8: TWO channels staged per iteration -> 64 back-to-back MMAs per barrier
// (halves barrier count, doubles MMA run length for overlap).

namespace fc {
constexpr int Cc = 64, OC = 64, Hh = 256, Ww = 256, Kk = 31, PD = 15;
constexpr int WSP = 40;       // ws pitch in halves -> LDS conflict-free
constexpr int NIT = (Cc / 2) * 32;  // 1024 iterations (c-pair x s)
}

#define MMA16816(d, a, b0v, b1v)                                            \
    asm volatile("mma.sync.aligned.m16n8k16.row.col.f32.f16.f16.f32 "       \
                 "{%0,%1,%2,%3}, {%4,%5,%6,%7}, {%8,%9}, {%0,%1,%2,%3};"    \
                 : "+f"((d)[0]), "+f"((d)[1]), "+f"((d)[2]), "+f"((d)[3])   \
                 : "r"((a)[0]), "r"((a)[1]), "r"((a)[2]), "r"((a)[3]),      \
                   "r"(b0v), "r"(b1v))

__global__ void __launch_bounds__(512, 1)
fftconv_fp16c2_kernel(const float* __restrict__ sig,
                      const float* __restrict__ wgt,
                      const float* __restrict__ bias,
                      float* __restrict__ out)
{
    using namespace fc;
    __shared__ __half2 rowp[2][2][288];      // [buf][ch][pair q]
    __shared__ __half  ws[4][2][64 * WSP];   // [ring slot][ch][oc*WSP + j]

    const int tid  = threadIdx.x;
    const int wid  = tid >> 5;
    const int lane = tid & 31;
    const int g    = lane >> 2;
    const int t4   = lane & 3;
    const int r    = wid >> 3;         // 0 -> row y0, 1 -> row y0+1
    const int wm   = (wid & 7) * 32;   // warp's 32-px M slice
    const int y0   = blockIdx.x * 2;
    const int b    = blockIdx.y;

    float acc[2][8][4];
#pragma unroll
    for (int mt = 0; mt < 2; ++mt)
#pragma unroll
        for (int nt = 0; nt < 8; ++nt)
#pragma unroll
            for (int q = 0; q < 4; ++q) acc[mt][nt][q] = 0.f;

    const float* sbase = sig + (size_t)b * Cc * Hh * Ww;

    // weight index bases: oc = e*16 + wid, j = lane
    size_t woff[4];
#pragma unroll
    for (int e = 0; e < 4; ++e)
        woff[e] = (size_t)(e * 16 + wid) * (Cc * Kk * Kk) + lane;
    const bool wlane = (lane < Kk);

    __half2 pfr[2];
    __half  pfw[2][4];
    // prefetch iteration (cp2, s2): input rows of channels 2cp2, 2cp2+1 at
    // yy = y0 + s2 - 15, plus weight slices i = s2 for both channels.
    auto prefetch = [&](int cp2, int s2) {
        const int yy = y0 + s2 - PD;
        const bool rowok = ((unsigned)yy < (unsigned)Hh);
        if (tid < 288) {
            const int x = tid - PD;
            const bool ok0 = rowok && (unsigned)x < (unsigned)Ww;
            const bool ok1 = rowok && (unsigned)(x + 1) < (unsigned)Ww;
#pragma unroll
            for (int ch = 0; ch < 2; ++ch) {
                const float* srow =
                    sbase + ((size_t)(2 * cp2 + ch) * Hh + (rowok ? yy : 0)) * Ww;
                const float f0 = ok0 ? srow[x] : 0.f;
                const float f1 = ok1 ? srow[x + 1] : 0.f;
                pfr[ch] = __floats2half2_rn(f0, f1);
            }
        }
        if (s2 < Kk) {
            const size_t cb = (size_t)(2 * cp2) * (Kk * Kk) + (size_t)s2 * Kk;
#pragma unroll
            for (int ch = 0; ch < 2; ++ch)
#pragma unroll
                for (int e = 0; e < 4; ++e)
                    pfw[ch][e] = wlane
                        ? __float2half_rn(wgt[woff[e] + cb + (size_t)ch * (Kk * Kk)])
                        : __half(__ushort_as_half(0));
        }
    };

    // ---- prologue: stage iteration 0 ----
    prefetch(0, 0);
    if (tid < 288) {
        rowp[0][0][tid] = pfr[0];
        rowp[0][1][tid] = pfr[1];
    }
#pragma unroll
    for (int ch = 0; ch < 2; ++ch)
#pragma unroll
        for (int e = 0; e < 4; ++e)
            ws[0][ch][(e * 16 + wid) * WSP + lane] = pfw[ch][e];
    __syncthreads();

    for (int t = 0; t < NIT; ++t) {
        const int s = t & 31;
        const bool more = (t + 1 < NIT);
        const int ns = (t + 1) & 31;
        const int ncp = (t + 1) >> 5;

        // ---- prefetch next iteration (LDG hides under 64 MMAs) ----
        if (more) prefetch(ncp, ns);

        // ---- compute: 2 channels x (2 mt x 8 nt x 2 kc) MMAs ----
        // group 0 (row y0):   i = s,   slot t&3      (valid s < 31)
        // group 1 (row y0+1): i = s-1, slot (t+3)&3  (valid s >= 1)
        const bool valid = r ? (s >= 1) : (s < Kk);
        if (valid) {
            const int slot = r ? ((t + 3) & 3) : (t & 3);
#pragma unroll
            for (int ch = 0; ch < 2; ++ch) {
                const uint32_t* rp = (const uint32_t*)rowp[t & 1][ch];
                const __half*   wb = ws[slot][ch];
#pragma unroll
                for (int mt = 0; mt < 2; ++mt) {
                    const int abase = wm + mt * 16 + g + 2 * t4;
                    uint32_t p[5];
#pragma unroll
                    for (int z = 0; z < 5; ++z) p[z] = rp[abase + 8 * z];
                    uint32_t a0[4] = {p[0], p[1], p[1], p[2]};  // taps 0-15
                    uint32_t a1[4] = {p[2], p[3], p[3], p[4]};  // taps 16-31
#pragma unroll
                    for (int nt = 0; nt < 8; ++nt) {
                        const uint32_t* wrow =
                            (const uint32_t*)(wb + (nt * 8 + g) * WSP) + t4;
                        const uint32_t b00 = wrow[0];
                        const uint32_t b01 = wrow[4];
                        const uint32_t b10 = wrow[8];
                        const uint32_t b11 = wrow[12];
                        MMA16816(acc[mt][nt], a0, b00, b01);
                        MMA16816(acc[mt][nt], a1, b10, b11);
                    }
                }
            }
        }

        // ---- store next buffers (distinct ring slots / row buf) ----
        if (more) {
            if (tid < 288) {
                rowp[(t + 1) & 1][0][tid] = pfr[0];
                rowp[(t + 1) & 1][1][tid] = pfr[1];
            }
            if (ns < Kk) {
                const int nslot = (t + 1) & 3;
#pragma unroll
                for (int ch = 0; ch < 2; ++ch)
#pragma unroll
                    for (int e = 0; e < 4; ++e)
                        ws[nslot][ch][(e * 16 + wid) * WSP + lane] = pfw[ch][e];
            }
        }
        __syncthreads();
    }

    // ---- epilogue ----
    const int yrow = y0 + r;
#pragma unroll
    for (int nt = 0; nt < 8; ++nt) {
        const int oc0 = nt * 8 + 2 * t4;
        const float bv0 = bias[oc0];
        const float bv1 = bias[oc0 + 1];
        float* p0 = out + (((size_t)b * OC + oc0) * Hh + yrow) * Ww;
        float* p1 = p0 + (size_t)Hh * Ww;
#pragma unroll
        for (int mt = 0; mt < 2; ++mt) {
            const int px = wm + mt * 16 + g;
            p0[px]     = acc[mt][nt][0] + bv0;
            p1[px]     = acc[mt][nt][1] + bv1;
            p0[px + 8] = acc[mt][nt][2] + bv0;
            p1[px + 8] = acc[mt][nt][3] + bv1;
        }
    }
}

extern "C" void kernel_launch(void* const* d_in, const int* in_sizes, int n_in,
                              void* d_out, int out_size)
{
    using namespace fc;
    const float* sig  = (const float*)d_in[0];  // (8, 64, 256, 256)
    const float* wgt  = (const float*)d_in[1];  // (64, 64, 31, 31)
    const float* bias = (const float*)d_in[2];  // (64,)
    float* out = (float*)d_out;                 // (8, 64, 256, 256) fp32

    dim3 grid(Hh / 2, 8);   // one CTA per (2 output rows, batch)
    fftconv_fp16c2_kernel<<<grid, 512>>>(sig, wgt, bias, out);
}

// round 10
// speedup vs baseline: 8.2902x; 1.0150x over previous
#include <cuda_runtime.h>
#include <cuda_fp16.h>
#include <cstdint>

// FFTConv2d == direct cross-correlation:
//   out[b,o,y,x] = sum_{c,i,j} sig[b,c,y+i-15,x+j-15] * w[o,c,i,j] + bias[o]
// Implicit GEMM, mma.sync m16n8k16 fp16. CTA = (b, y0..y0+1), 16 warps:
// warps 0-7 accumulate row y0 (i=s), warps 8-15 row y0+1 (i=s-1).
// R9: FOUR channels staged per iteration -> 128 back-to-back MMAs per
// barrier (NIT=512). Dynamic smem (~91KB), 1 CTA/SM.

namespace fc {
constexpr int Cc = 64, OC = 64, Hh = 256, Ww = 256, Kk = 31, PD = 15;
constexpr int WSP = 40;             // ws pitch in halves -> LDS conflict-free
constexpr int CH  = 4;              // channels per iteration
constexpr int NIT = (Cc / CH) * 32; // 512 iterations
constexpr int WS_CH   = 64 * WSP;          // halves per (slot, ch) = 2560
constexpr int ROW_ELE = 288;               // half2 pairs per row
// dynamic smem layout (bytes)
constexpr uint32_t ROW_BYTES = 2 * CH * ROW_ELE * 4;       // 9216
constexpr uint32_t WS_BYTES  = 4 * CH * WS_CH * 2;         // 81920
constexpr uint32_t SMEM_BYTES = ROW_BYTES + WS_BYTES;      // 91136
}

#define MMA16816(d, a, b0v, b1v)                                            \
    asm volatile("mma.sync.aligned.m16n8k16.row.col.f32.f16.f16.f32 "       \
                 "{%0,%1,%2,%3}, {%4,%5,%6,%7}, {%8,%9}, {%0,%1,%2,%3};"    \
                 : "+f"((d)[0]), "+f"((d)[1]), "+f"((d)[2]), "+f"((d)[3])   \
                 : "r"((a)[0]), "r"((a)[1]), "r"((a)[2]), "r"((a)[3]),      \
                   "r"(b0v), "r"(b1v))

__global__ void __launch_bounds__(512, 1)
fftconv_fp16c4_kernel(const float* __restrict__ sig,
                      const float* __restrict__ wgt,
                      const float* __restrict__ bias,
                      float* __restrict__ out)
{
    using namespace fc;
    extern __shared__ __align__(16) char dsm[];
    // rowp[buf][ch][q]: {half(row[q]), half(row[q+1])}
    __half2 (*rowp)[CH][ROW_ELE] = (__half2 (*)[CH][ROW_ELE])dsm;
    // ws[slot][ch][oc*WSP + j]
    __half (*ws)[CH][WS_CH] = (__half (*)[CH][WS_CH])(dsm + ROW_BYTES);

    const int tid  = threadIdx.x;
    const int wid  = tid >> 5;
    const int lane = tid & 31;
    const int g    = lane >> 2;
    const int t4   = lane & 3;
    const int r    = wid >> 3;         // 0 -> row y0, 1 -> row y0+1
    const int wm   = (wid & 7) * 32;   // warp's 32-px M slice
    const int y0   = blockIdx.x * 2;
    const int b    = blockIdx.y;

    float acc[2][8][4];
#pragma unroll
    for (int mt = 0; mt < 2; ++mt)
#pragma unroll
        for (int nt = 0; nt < 8; ++nt)
#pragma unroll
            for (int q = 0; q < 4; ++q) acc[mt][nt][q] = 0.f;

    const float* sbase = sig + (size_t)b * Cc * Hh * Ww;

    // weight index bases: oc = e*16 + wid, j = lane
    size_t woff[4];
#pragma unroll
    for (int e = 0; e < 4; ++e)
        woff[e] = (size_t)(e * 16 + wid) * (Cc * Kk * Kk) + lane;
    const bool wlane = (lane < Kk);

    __half2 pfr[CH];
    __half  pfw[CH][4];
    // prefetch iteration (cq2, s2): rows of channels CH*cq2+ch at
    // yy = y0 + s2 - 15, plus weight slices i = s2 for those channels.
    auto prefetch = [&](int cq2, int s2) {
        const int yy = y0 + s2 - PD;
        const bool rowok = ((unsigned)yy < (unsigned)Hh);
        if (tid < ROW_ELE) {
            const int x = tid - PD;
            const bool ok0 = rowok && (unsigned)x < (unsigned)Ww;
            const bool ok1 = rowok && (unsigned)(x + 1) < (unsigned)Ww;
#pragma unroll
            for (int ch = 0; ch < CH; ++ch) {
                const float* srow =
                    sbase + ((size_t)(CH * cq2 + ch) * Hh + (rowok ? yy : 0)) * Ww;
                const float f0 = ok0 ? srow[x] : 0.f;
                const float f1 = ok1 ? srow[x + 1] : 0.f;
                pfr[ch] = __floats2half2_rn(f0, f1);
            }
        }
        if (s2 < Kk) {
            const size_t cb = (size_t)(CH * cq2) * (Kk * Kk) + (size_t)s2 * Kk;
#pragma unroll
            for (int ch = 0; ch < CH; ++ch)
#pragma unroll
                for (int e = 0; e < 4; ++e)
                    pfw[ch][e] = wlane
                        ? __float2half_rn(wgt[woff[e] + cb + (size_t)ch * (Kk * Kk)])
                        : __half(__ushort_as_half(0));
        }
    };

    // ---- prologue: stage iteration 0 ----
    prefetch(0, 0);
    if (tid < ROW_ELE)
#pragma unroll
        for (int ch = 0; ch < CH; ++ch) rowp[0][ch][tid] = pfr[ch];
#pragma unroll
    for (int ch = 0; ch < CH; ++ch)
#pragma unroll
        for (int e = 0; e < 4; ++e)
            ws[0][ch][(e * 16 + wid) * WSP + lane] = pfw[ch][e];
    __syncthreads();

    for (int t = 0; t < NIT; ++t) {
        const int s = t & 31;
        const bool more = (t + 1 < NIT);
        const int ns = (t + 1) & 31;
        const int ncq = (t + 1) >> 5;

        // ---- prefetch next iteration (LDG hides under 128 MMAs) ----
        if (more) prefetch(ncq, ns);

        // ---- compute: CH channels x (2 mt x 8 nt x 2 kc) MMAs ----
        // group 0 (row y0):   i = s,   slot t&3      (valid s < 31)
        // group 1 (row y0+1): i = s-1, slot (t+3)&3  (valid s >= 1)
        const bool valid = r ? (s >= 1) : (s < Kk);
        if (valid) {
            const int slot = r ? ((t + 3) & 3) : (t & 3);
#pragma unroll
            for (int ch = 0; ch < CH; ++ch) {
                const uint32_t* rp = (const uint32_t*)rowp[t & 1][ch];
                const __half*   wb = ws[slot][ch];
#pragma unroll
                for (int mt = 0; mt < 2; ++mt) {
                    const int abase = wm + mt * 16 + g + 2 * t4;
                    uint32_t p[5];
#pragma unroll
                    for (int z = 0; z < 5; ++z) p[z] = rp[abase + 8 * z];
                    uint32_t a0[4] = {p[0], p[1], p[1], p[2]};  // taps 0-15
                    uint32_t a1[4] = {p[2], p[3], p[3], p[4]};  // taps 16-31
#pragma unroll
                    for (int nt = 0; nt < 8; ++nt) {
                        const uint32_t* wrow =
                            (const uint32_t*)(wb + (nt * 8 + g) * WSP) + t4;
                        const uint32_t b00 = wrow[0];
                        const uint32_t b01 = wrow[4];
                        const uint32_t b10 = wrow[8];
                        const uint32_t b11 = wrow[12];
                        MMA16816(acc[mt][nt], a0, b00, b01);
                        MMA16816(acc[mt][nt], a1, b10, b11);
                    }
                }
            }
        }

        // ---- store next buffers (distinct ring slots / row buf) ----
        if (more) {
            if (tid < ROW_ELE)
#pragma unroll
                for (int ch = 0; ch < CH; ++ch)
                    rowp[(t + 1) & 1][ch][tid] = pfr[ch];
            if (ns < Kk) {
                const int nslot = (t + 1) & 3;
#pragma unroll
                for (int ch = 0; ch < CH; ++ch)
#pragma unroll
                    for (int e = 0; e < 4; ++e)
                        ws[nslot][ch][(e * 16 + wid) * WSP + lane] = pfw[ch][e];
            }
        }
        __syncthreads();
    }

    // ---- epilogue ----
    const int yrow = y0 + r;
#pragma unroll
    for (int nt = 0; nt < 8; ++nt) {
        const int oc0 = nt * 8 + 2 * t4;
        const float bv0 = bias[oc0];
        const float bv1 = bias[oc0 + 1];
        float* p0 = out + (((size_t)b * OC + oc0) * Hh + yrow) * Ww;
        float* p1 = p0 + (size_t)Hh * Ww;
#pragma unroll
        for (int mt = 0; mt < 2; ++mt) {
            const int px = wm + mt * 16 + g;
            p0[px]     = acc[mt][nt][0] + bv0;
            p1[px]     = acc[mt][nt][1] + bv1;
            p0[px + 8] = acc[mt][nt][2] + bv0;
            p1[px + 8] = acc[mt][nt][3] + bv1;
        }
    }
}

extern "C" void kernel_launch(void* const* d_in, const int* in_sizes, int n_in,
                              void* d_out, int out_size)
{
    using namespace fc;
    const float* sig  = (const float*)d_in[0];  // (8, 64, 256, 256)
    const float* wgt  = (const float*)d_in[1];  // (64, 64, 31, 31)
    const float* bias = (const float*)d_in[2];  // (64,)
    float* out = (float*)d_out;                 // (8, 64, 256, 256) fp32

    cudaFuncSetAttribute(fftconv_fp16c4_kernel,
                         cudaFuncAttributeMaxDynamicSharedMemorySize, SMEM_BYTES);
    dim3 grid(Hh / 2, 8);   // one CTA per (2 output rows, batch)
    fftconv_fp16c4_kernel<<<grid, 512, SMEM_BYTES>>>(sig, wgt, bias, out);
}

// round 11
// speedup vs baseline: 10.1025x; 1.2186x over previous
#include <cuda_runtime.h>
#include <cuda_fp16.h>
#include <cstdint>

// FFTConv2d == direct cross-correlation:
//   out[b,o,y,x] = sum_{c,i,j} sig[b,c,y+i-15,x+j-15] * w[o,c,i,j] + bias[o]
// R10: two pre-pass kernels convert operands to fp16 staging images in
// __device__ globals (padding baked in); main kernel stages via cp.async
// (no register staging, no cvt, no branches), ring-5 async pipeline,
// depth 3, one barrier per 128-MMA burst. Compute mapping as R8/R9:
// CTA = (b, y0..y0+1), warps 0-7 row y0 (i=s), warps 8-15 row y0+1 (i=s-1).

namespace fc {
constexpr int Cc = 64, OC = 64, Hh = 256, Ww = 256, Kk = 31, PD = 15;
constexpr int WSP = 40;              // ws pitch in halves (20 words)
constexpr int CH = 4;                // channels per stage
constexpr int NIT = (Cc / CH) * 32;  // 512 iterations
constexpr int NSTG = 5;              // smem ring stages
constexpr int ROWP = 288;            // half2 pairs per staged row
constexpr int YPAD = 286;            // padded input rows per (b,c)
// stage layout (bytes): rows CH*1152, then ws CH*5120
constexpr uint32_t ROW_B   = ROWP * 4;           // 1152
constexpr uint32_t WS_B    = 64 * WSP * 2;       // 5120
constexpr uint32_t STAGE_B = CH * ROW_B + CH * WS_B;   // 25088
constexpr uint32_t SMEM_BYTES = NSTG * STAGE_B;        // 125440
}

// ---- scratch (uninitialized __device__ globals: no allocation) ----
__device__ __half2 g_pair[8][64][fc::YPAD][fc::ROWP];     // ~169 MB
__device__ __half  g_ws[fc::Cc * fc::Kk][64 * fc::WSP];   // ~10 MB

#define MMA16816(d, a, b0v, b1v)                                            \
    asm volatile("mma.sync.aligned.m16n8k16.row.col.f32.f16.f16.f32 "       \
                 "{%0,%1,%2,%3}, {%4,%5,%6,%7}, {%8,%9}, {%0,%1,%2,%3};"    \
                 : "+f"((d)[0]), "+f"((d)[1]), "+f"((d)[2]), "+f"((d)[3])   \
                 : "r"((a)[0]), "r"((a)[1]), "r"((a)[2]), "r"((a)[3]),      \
                   "r"(b0v), "r"(b1v))

#define CP16(dst, src) \
    asm volatile("cp.async.cg.shared.global [%0], [%1], 16;" \
                 :: "r"(dst), "l"(src) : "memory")
#define CP_COMMIT() asm volatile("cp.async.commit_group;" ::: "memory")
#define CP_WAIT2()  asm volatile("cp.async.wait_group 2;" ::: "memory")

__device__ __forceinline__ uint32_t smem_u32(const void* p) {
    uint32_t a;
    asm("{ .reg .u64 t; cvta.to.shared.u64 t, %1; cvt.u32.u64 %0, t; }"
        : "=r"(a) : "l"(p));
    return a;
}

// ---- pre-pass 1: pair-duplicated fp16 rows with padding baked in ----
__global__ void build_pairs(const float* __restrict__ sig) {
    using namespace fc;
    const int q  = threadIdx.x;       // 0..287
    const int yp = blockIdx.x;        // 0..285 (yy = yp - 15)
    const int c  = blockIdx.y;
    const int b  = blockIdx.z;
    const int yy = yp - PD;
    const bool rowok = ((unsigned)yy < (unsigned)Hh);
    const float* srow = sig + (((size_t)b * Cc + c) * Hh + (rowok ? yy : 0)) * Ww;
    const int x = q - PD;
    const float f0 = (rowok && (unsigned)x < (unsigned)Ww) ? srow[x] : 0.f;
    const float f1 = (rowok && (unsigned)(x + 1) < (unsigned)Ww) ? srow[x + 1] : 0.f;
    g_pair[b][c][yp][q] = __floats2half2_rn(f0, f1);
}

// ---- pre-pass 2: weight slice smem images (64 oc x 40 halves, j>=31 = 0) ----
__global__ void build_ws(const float* __restrict__ wgt) {
    using namespace fc;
    const int ci = blockIdx.x;        // c*31 + s
    const int c  = ci / Kk;
    const int s  = ci - c * Kk;
    for (int k = threadIdx.x; k < 64 * WSP; k += blockDim.x) {
        const int oc = k / WSP;
        const int j  = k - oc * WSP;
        const float v = (j < Kk)
            ? wgt[(((size_t)oc * Cc + c) * Kk + s) * Kk + j] : 0.f;
        g_ws[ci][k] = __float2half_rn(v);
    }
}

// ---- main kernel ----
__global__ void __launch_bounds__(512, 1)
fftconv_cpasync_kernel(const float* __restrict__ bias,
                       float* __restrict__ out)
{
    using namespace fc;
    extern __shared__ __align__(16) char dsm[];
    const uint32_t sbase = smem_u32(dsm);

    const int tid  = threadIdx.x;
    const int wid  = tid >> 5;
    const int lane = tid & 31;
    const int g    = lane >> 2;
    const int t4   = lane & 3;
    const int r    = wid >> 3;         // 0 -> row y0, 1 -> row y0+1
    const int wm   = (wid & 7) * 32;   // warp's 32-px M slice
    const int y0   = blockIdx.x * 2;
    const int b    = blockIdx.y;

    float acc[2][8][4];
#pragma unroll
    for (int mt = 0; mt < 2; ++mt)
#pragma unroll
        for (int nt = 0; nt < 8; ++nt)
#pragma unroll
            for (int q = 0; q < 4; ++q) acc[mt][nt][q] = 0.f;

    // issue cp.asyncs for iteration u into slot u % NSTG, then commit.
    auto issue_stage = [&](int u) {
        const int s    = u & 31;
        const int cq   = u >> 5;             // channel quad
        const uint32_t base = sbase + (uint32_t)(u % NSTG) * STAGE_B;
        // rows: CH x 288 half2 (72 x 16B each)
        for (int k = tid; k < CH * 72; k += 512) {
            const int ch = k / 72;
            const int e  = k - ch * 72;
            const char* src =
                (const char*)&g_pair[b][CH * cq + ch][y0 + s][0] + e * 16;
            CP16(base + (uint32_t)ch * ROW_B + (uint32_t)e * 16, src);
        }
        // weight slices: CH x 5120B (320 x 16B each); skip at s == 31
        if (s < Kk) {
            for (int k = tid; k < CH * 320; k += 512) {
                const int ch = k / 320;
                const int e  = k - ch * 320;
                const char* src =
                    (const char*)&g_ws[(CH * cq + ch) * Kk + s][0] + e * 16;
                CP16(base + CH * ROW_B + (uint32_t)ch * WS_B + (uint32_t)e * 16,
                     src);
            }
        }
        CP_COMMIT();
    };

    // ---- prologue: fill pipeline with stages 0..2 ----
    issue_stage(0);
    issue_stage(1);
    issue_stage(2);

    for (int t = 0; t < NIT; ++t) {
        const int s = t & 31;

        CP_WAIT2();          // stage t landed (<=2 younger groups outstanding)
        __syncthreads();     // visible to all; all warps done with iter t-1

        // ---- compute: CH channels x (2 mt x 8 nt x 2 kc) MMAs ----
        // group 0 (row y0):   i = s,   slot t%5      (valid s < 31)
        // group 1 (row y0+1): i = s-1, slot (t+4)%5  (valid s >= 1)
        const bool valid = r ? (s >= 1) : (s < Kk);
        if (valid) {
            const uint32_t rbase = sbase + (uint32_t)(t % NSTG) * STAGE_B;
            const uint32_t wslot = r ? ((t + 4) % NSTG) : (t % NSTG);
            const uint32_t wbase = sbase + wslot * STAGE_B + CH * ROW_B;
#pragma unroll
            for (int ch = 0; ch < CH; ++ch) {
                const uint32_t* rp =
                    (const uint32_t*)(dsm + (rbase - sbase) + ch * ROW_B);
                const __half* wb =
                    (const __half*)(dsm + (wbase - sbase) + ch * WS_B);
#pragma unroll
                for (int mt = 0; mt < 2; ++mt) {
                    const int abase = wm + mt * 16 + g + 2 * t4;
                    uint32_t p[5];
#pragma unroll
                    for (int z = 0; z < 5; ++z) p[z] = rp[abase + 8 * z];
                    uint32_t a0[4] = {p[0], p[1], p[1], p[2]};  // taps 0-15
                    uint32_t a1[4] = {p[2], p[3], p[3], p[4]};  // taps 16-31
#pragma unroll
                    for (int nt = 0; nt < 8; ++nt) {
                        const uint32_t* wrow =
                            (const uint32_t*)(wb + (nt * 8 + g) * WSP) + t4;
                        const uint32_t b00 = wrow[0];
                        const uint32_t b01 = wrow[4];
                        const uint32_t b10 = wrow[8];
                        const uint32_t b11 = wrow[12];
                        MMA16816(acc[mt][nt], a0, b00, b01);
                        MMA16816(acc[mt][nt], a1, b10, b11);
                    }
                }
            }
        }

        // ---- issue stage t+3 (slot (t+3)%5; its last readers were iter t-1,
        //      and every warp past this iteration's barrier finished t-1) ----
        if (t + 3 < NIT) issue_stage(t + 3);
        else CP_COMMIT();   // keep group count uniform for wait_group
    }

    // ---- epilogue ----
    const int yrow = y0 + r;
#pragma unroll
    for (int nt = 0; nt < 8; ++nt) {
        const int oc0 = nt * 8 + 2 * t4;
        const float bv0 = bias[oc0];
        const float bv1 = bias[oc0 + 1];
        float* p0 = out + (((size_t)b * OC + oc0) * Hh + yrow) * Ww;
        float* p1 = p0 + (size_t)Hh * Ww;
#pragma unroll
        for (int mt = 0; mt < 2; ++mt) {
            const int px = wm + mt * 16 + g;
            p0[px]     = acc[mt][nt][0] + bv0;
            p1[px]     = acc[mt][nt][1] + bv1;
            p0[px + 8] = acc[mt][nt][2] + bv0;
            p1[px + 8] = acc[mt][nt][3] + bv1;
        }
    }
}

extern "C" void kernel_launch(void* const* d_in, const int* in_sizes, int n_in,
                              void* d_out, int out_size)
{
    using namespace fc;
    const float* sig  = (const float*)d_in[0];  // (8, 64, 256, 256)
    const float* wgt  = (const float*)d_in[1];  // (64, 64, 31, 31)
    const float* bias = (const float*)d_in[2];  // (64,)
    float* out = (float*)d_out;                 // (8, 64, 256, 256) fp32

    // pre-pass: build fp16 staging images (deterministic, every call)
    build_pairs<<<dim3(YPAD, Cc, 8), ROWP>>>(sig);
    build_ws<<<Cc * Kk, 256>>>(wgt);

    cudaFuncSetAttribute(fftconv_cpasync_kernel,
                         cudaFuncAttributeMaxDynamicSharedMemorySize, SMEM_BYTES);
    dim3 grid(Hh / 2, 8);   // one CTA per (2 output rows, batch)
    fftconv_cpasync_kernel<<<grid, 512, SMEM_BYTES>>>(bias, out);
}

// round 12
// speedup vs baseline: 10.8145x; 1.0705x over previous
#include <cuda_runtime.h>
#include <cuda_fp16.h>
#include <cstdint>

// FFTConv2d == direct cross-correlation:
//   out[b,o,y,x] = sum_{c,i,j} sig[b,c,y+i-15,x+j-15] * w[o,c,i,j] + bias[o]
// R11: pre-pass converts operands to fp16 staging images in __device__
// globals (padding baked in); main kernel stages via cp.async only.
// CH=8 channels per stage -> 256 back-to-back MMAs per barrier (NIT=256),
// ring-4 smem (200KB), depth-2 pipeline (wait_group 1).
// CTA = (b, y0..y0+1), warps 0-7 row y0 (i=s), warps 8-15 row y0+1 (i=s-1).

namespace fc {
constexpr int Cc = 64, OC = 64, Hh = 256, Ww = 256, Kk = 31, PD = 15;
constexpr int WSP = 40;              // ws pitch in halves (20 words)
constexpr int CH = 8;                // channels per stage
constexpr int NIT = (Cc / CH) * 32;  // 256 iterations
constexpr int NSTG = 4;              // smem ring stages
constexpr int ROWP = 288;            // half2 pairs per staged row
constexpr int YPAD = 286;            // padded input rows per (b,c)
constexpr uint32_t ROW_B   = ROWP * 4;                 // 1152
constexpr uint32_t WS_B    = 64 * WSP * 2;             // 5120
constexpr uint32_t STAGE_B = CH * ROW_B + CH * WS_B;   // 50176
constexpr uint32_t SMEM_BYTES = NSTG * STAGE_B;        // 200704
}

// ---- scratch (uninitialized __device__ globals: no allocation) ----
__device__ __half2 g_pair[8][64][fc::YPAD][fc::ROWP];     // ~169 MB
__device__ __half  g_ws[fc::Cc * fc::Kk][64 * fc::WSP];   // ~10 MB

#define MMA16816(d, a, b0v, b1v)                                            \
    asm volatile("mma.sync.aligned.m16n8k16.row.col.f32.f16.f16.f32 "       \
                 "{%0,%1,%2,%3}, {%4,%5,%6,%7}, {%8,%9}, {%0,%1,%2,%3};"    \
                 : "+f"((d)[0]), "+f"((d)[1]), "+f"((d)[2]), "+f"((d)[3])   \
                 : "r"((a)[0]), "r"((a)[1]), "r"((a)[2]), "r"((a)[3]),      \
                   "r"(b0v), "r"(b1v))

#define CP16(dst, src) \
    asm volatile("cp.async.cg.shared.global [%0], [%1], 16;" \
                 :: "r"(dst), "l"(src) : "memory")
#define CP_COMMIT() asm volatile("cp.async.commit_group;" ::: "memory")
#define CP_WAIT1()  asm volatile("cp.async.wait_group 1;" ::: "memory")

__device__ __forceinline__ uint32_t smem_u32(const void* p) {
    uint32_t a;
    asm("{ .reg .u64 t; cvta.to.shared.u64 t, %1; cvt.u32.u64 %0, t; }"
        : "=r"(a) : "l"(p));
    return a;
}

// ---- pre-pass 1: pair-duplicated fp16 rows with padding baked in ----
__global__ void build_pairs(const float* __restrict__ sig) {
    using namespace fc;
    const int q  = threadIdx.x;       // 0..287
    const int yp = blockIdx.x;        // 0..285 (yy = yp - 15)
    const int c  = blockIdx.y;
    const int b  = blockIdx.z;
    const int yy = yp - PD;
    const bool rowok = ((unsigned)yy < (unsigned)Hh);
    const float* srow = sig + (((size_t)b * Cc + c) * Hh + (rowok ? yy : 0)) * Ww;
    const int x = q - PD;
    const float f0 = (rowok && (unsigned)x < (unsigned)Ww) ? srow[x] : 0.f;
    const float f1 = (rowok && (unsigned)(x + 1) < (unsigned)Ww) ? srow[x + 1] : 0.f;
    g_pair[b][c][yp][q] = __floats2half2_rn(f0, f1);
}

// ---- pre-pass 2: weight slice smem images (64 oc x 40 halves, j>=31 = 0) ----
__global__ void build_ws(const float* __restrict__ wgt) {
    using namespace fc;
    const int ci = blockIdx.x;        // c*31 + s
    const int c  = ci / Kk;
    const int s  = ci - c * Kk;
    for (int k = threadIdx.x; k < 64 * WSP; k += blockDim.x) {
        const int oc = k / WSP;
        const int j  = k - oc * WSP;
        const float v = (j < Kk)
            ? wgt[(((size_t)oc * Cc + c) * Kk + s) * Kk + j] : 0.f;
        g_ws[ci][k] = __float2half_rn(v);
    }
}

// ---- main kernel ----
__global__ void __launch_bounds__(512, 1)
fftconv_cpasync8_kernel(const float* __restrict__ bias,
                        float* __restrict__ out)
{
    using namespace fc;
    extern __shared__ __align__(16) char dsm[];
    const uint32_t sbase = smem_u32(dsm);

    const int tid  = threadIdx.x;
    const int wid  = tid >> 5;
    const int lane = tid & 31;
    const int g    = lane >> 2;
    const int t4   = lane & 3;
    const int r    = wid >> 3;         // 0 -> row y0, 1 -> row y0+1
    const int wm   = (wid & 7) * 32;   // warp's 32-px M slice
    const int y0   = blockIdx.x * 2;
    const int b    = blockIdx.y;

    float acc[2][8][4];
#pragma unroll
    for (int mt = 0; mt < 2; ++mt)
#pragma unroll
        for (int nt = 0; nt < 8; ++nt)
#pragma unroll
            for (int q = 0; q < 4; ++q) acc[mt][nt][q] = 0.f;

    // issue cp.asyncs for iteration u into slot u % NSTG, then commit.
    auto issue_stage = [&](int u) {
        const int s  = u & 31;
        const int cq = u >> 5;               // channel octet
        const uint32_t base = sbase + (uint32_t)(u % NSTG) * STAGE_B;
        // rows: CH x 288 half2 (72 x 16B each) = 576 CP16 per CTA
        for (int k = tid; k < CH * 72; k += 512) {
            const int ch = k / 72;
            const int e  = k - ch * 72;
            const char* src =
                (const char*)&g_pair[b][CH * cq + ch][y0 + s][0] + e * 16;
            CP16(base + (uint32_t)ch * ROW_B + (uint32_t)e * 16, src);
        }
        // weight slices: CH x 5120B (320 x 16B each); skip at s == 31
        if (s < Kk) {
            for (int k = tid; k < CH * 320; k += 512) {
                const int ch = k / 320;
                const int e  = k - ch * 320;
                const char* src =
                    (const char*)&g_ws[(CH * cq + ch) * Kk + s][0] + e * 16;
                CP16(base + CH * ROW_B + (uint32_t)ch * WS_B + (uint32_t)e * 16,
                     src);
            }
        }
        CP_COMMIT();
    };

    // ---- prologue: fill pipeline with stages 0..1 ----
    issue_stage(0);
    issue_stage(1);

    for (int t = 0; t < NIT; ++t) {
        const int s = t & 31;

        CP_WAIT1();          // stage t landed (<=1 younger group outstanding)
        __syncthreads();     // visible to all; all warps done with iter t-1

        // ---- compute: CH channels x (2 mt x 8 nt x 2 kc) MMAs ----
        // group 0 (row y0):   i = s,   slot t%4      (valid s < 31)
        // group 1 (row y0+1): i = s-1, slot (t+3)%4  (valid s >= 1)
        const bool valid = r ? (s >= 1) : (s < Kk);
        if (valid) {
            const uint32_t roff = (uint32_t)(t % NSTG) * STAGE_B;
            const uint32_t wsl  = r ? ((t + 3) % NSTG) : (t % NSTG);
            const uint32_t woff = wsl * STAGE_B + CH * ROW_B;
#pragma unroll
            for (int ch = 0; ch < CH; ++ch) {
                const uint32_t* rp = (const uint32_t*)(dsm + roff + ch * ROW_B);
                const __half*   wb = (const __half*)(dsm + woff + ch * WS_B);
#pragma unroll
                for (int mt = 0; mt < 2; ++mt) {
                    const int abase = wm + mt * 16 + g + 2 * t4;
                    uint32_t p[5];
#pragma unroll
                    for (int z = 0; z < 5; ++z) p[z] = rp[abase + 8 * z];
                    uint32_t a0[4] = {p[0], p[1], p[1], p[2]};  // taps 0-15
                    uint32_t a1[4] = {p[2], p[3], p[3], p[4]};  // taps 16-31
#pragma unroll
                    for (int nt = 0; nt < 8; ++nt) {
                        const uint32_t* wrow =
                            (const uint32_t*)(wb + (nt * 8 + g) * WSP) + t4;
                        const uint32_t b00 = wrow[0];
                        const uint32_t b01 = wrow[4];
                        const uint32_t b10 = wrow[8];
                        const uint32_t b11 = wrow[12];
                        MMA16816(acc[mt][nt], a0, b00, b01);
                        MMA16816(acc[mt][nt], a1, b10, b11);
                    }
                }
            }
        }

        // ---- issue stage t+2 into slot (t+2)%4 = (t-2)%4: its last readers
        //      ran in iter t-1 (weights, group 1), and every warp past this
        //      iteration's barrier has finished iter t-1 -> race-free ----
        if (t + 2 < NIT) issue_stage(t + 2);
        else CP_COMMIT();   // keep group count uniform for wait_group
    }

    // ---- epilogue ----
    const int yrow = y0 + r;
#pragma unroll
    for (int nt = 0; nt < 8; ++nt) {
        const int oc0 = nt * 8 + 2 * t4;
        const float bv0 = bias[oc0];
        const float bv1 = bias[oc0 + 1];
        float* p0 = out + (((size_t)b * OC + oc0) * Hh + yrow) * Ww;
        float* p1 = p0 + (size_t)Hh * Ww;
#pragma unroll
        for (int mt = 0; mt < 2; ++mt) {
            const int px = wm + mt * 16 + g;
            p0[px]     = acc[mt][nt][0] + bv0;
            p1[px]     = acc[mt][nt][1] + bv1;
            p0[px + 8] = acc[mt][nt][2] + bv0;
            p1[px + 8] = acc[mt][nt][3] + bv1;
        }
    }
}

extern "C" void kernel_launch(void* const* d_in, const int* in_sizes, int n_in,
                              void* d_out, int out_size)
{
    using namespace fc;
    const float* sig  = (const float*)d_in[0];  // (8, 64, 256, 256)
    const float* wgt  = (const float*)d_in[1];  // (64, 64, 31, 31)
    const float* bias = (const float*)d_in[2];  // (64,)
    float* out = (float*)d_out;                 // (8, 64, 256, 256) fp32

    // pre-pass: build fp16 staging images (deterministic, every call)
    build_pairs<<<dim3(YPAD, Cc, 8), ROWP>>>(sig);
    build_ws<<<Cc * Kk, 256>>>(wgt);

    cudaFuncSetAttribute(fftconv_cpasync8_kernel,
                         cudaFuncAttributeMaxDynamicSharedMemorySize, SMEM_BYTES);
    dim3 grid(Hh / 2, 8);   // one CTA per (2 output rows, batch)
    fftconv_cpasync8_kernel<<<grid, 512, SMEM_BYTES>>>(bias, out);
}

// round 13
// speedup vs baseline: 10.8991x; 1.0078x over previous
#include <cuda_runtime.h>
#include <cuda_fp16.h>
#include <cstdint>

// FFTConv2d == direct cross-correlation:
//   out[b,o,y,x] = sum_{c,i,j} sig[b,c,y+i-15,x+j-15] * w[o,c,i,j] + bias[o]
// R12: warp tile reshaped 32px x 64oc -> 64px x 32oc (mt=4, nt=4) to cut
// redundant B-fragment LDS traffic ~30% (crossbar was co-limiting).
// Staging unchanged from R11: pre-pass fp16 images, cp.async ring-4 depth-2,
// CH=8 channels/stage, 256-MMA bursts per barrier.
// CTA = (b, y0..y0+1); warps 0-7 row y0 (i=s), warps 8-15 row y0+1 (i=s-1).

namespace fc {
constexpr int Cc = 64, OC = 64, Hh = 256, Ww = 256, Kk = 31, PD = 15;
constexpr int WSP = 40;              // ws pitch in halves (20 words)
constexpr int CH = 8;                // channels per stage
constexpr int NIT = (Cc / CH) * 32;  // 256 iterations
constexpr int NSTG = 4;              // smem ring stages
constexpr int ROWP = 288;            // half2 pairs per staged row
constexpr int YPAD = 286;            // padded input rows per (b,c)
constexpr uint32_t ROW_B   = ROWP * 4;                 // 1152
constexpr uint32_t WS_B    = 64 * WSP * 2;             // 5120
constexpr uint32_t STAGE_B = CH * ROW_B + CH * WS_B;   // 50176
constexpr uint32_t SMEM_BYTES = NSTG * STAGE_B;        // 200704
}

// ---- scratch (uninitialized __device__ globals: no allocation) ----
__device__ __half2 g_pair[8][64][fc::YPAD][fc::ROWP];     // ~169 MB
__device__ __half  g_ws[fc::Cc * fc::Kk][64 * fc::WSP];   // ~10 MB

#define MMA16816(d, a, b0v, b1v)                                            \
    asm volatile("mma.sync.aligned.m16n8k16.row.col.f32.f16.f16.f32 "       \
                 "{%0,%1,%2,%3}, {%4,%5,%6,%7}, {%8,%9}, {%0,%1,%2,%3};"    \
                 : "+f"((d)[0]), "+f"((d)[1]), "+f"((d)[2]), "+f"((d)[3])   \
                 : "r"((a)[0]), "r"((a)[1]), "r"((a)[2]), "r"((a)[3]),      \
                   "r"(b0v), "r"(b1v))

#define CP16(dst, src) \
    asm volatile("cp.async.cg.shared.global [%0], [%1], 16;" \
                 :: "r"(dst), "l"(src) : "memory")
#define CP_COMMIT() asm volatile("cp.async.commit_group;" ::: "memory")
#define CP_WAIT1()  asm volatile("cp.async.wait_group 1;" ::: "memory")

__device__ __forceinline__ uint32_t smem_u32(const void* p) {
    uint32_t a;
    asm("{ .reg .u64 t; cvta.to.shared.u64 t, %1; cvt.u32.u64 %0, t; }"
        : "=r"(a) : "l"(p));
    return a;
}

// ---- pre-pass 1: pair-duplicated fp16 rows with padding baked in ----
__global__ void build_pairs(const float* __restrict__ sig) {
    using namespace fc;
    const int q  = threadIdx.x;       // 0..287
    const int yp = blockIdx.x;        // 0..285 (yy = yp - 15)
    const int c  = blockIdx.y;
    const int b  = blockIdx.z;
    const int yy = yp - PD;
    const bool rowok = ((unsigned)yy < (unsigned)Hh);
    const float* srow = sig + (((size_t)b * Cc + c) * Hh + (rowok ? yy : 0)) * Ww;
    const int x = q - PD;
    const float f0 = (rowok && (unsigned)x < (unsigned)Ww) ? srow[x] : 0.f;
    const float f1 = (rowok && (unsigned)(x + 1) < (unsigned)Ww) ? srow[x + 1] : 0.f;
    g_pair[b][c][yp][q] = __floats2half2_rn(f0, f1);
}

// ---- pre-pass 2: weight slice smem images (64 oc x 40 halves, j>=31 = 0) ----
__global__ void build_ws(const float* __restrict__ wgt) {
    using namespace fc;
    const int ci = blockIdx.x;        // c*31 + s
    const int c  = ci / Kk;
    const int s  = ci - c * Kk;
    for (int k = threadIdx.x; k < 64 * WSP; k += blockDim.x) {
        const int oc = k / WSP;
        const int j  = k - oc * WSP;
        const float v = (j < Kk)
            ? wgt[(((size_t)oc * Cc + c) * Kk + s) * Kk + j] : 0.f;
        g_ws[ci][k] = __float2half_rn(v);
    }
}

// ---- main kernel ----
__global__ void __launch_bounds__(512, 1)
fftconv_m64n32_kernel(const float* __restrict__ bias,
                      float* __restrict__ out)
{
    using namespace fc;
    extern __shared__ __align__(16) char dsm[];
    const uint32_t sbase = smem_u32(dsm);

    const int tid  = threadIdx.x;
    const int wid  = tid >> 5;
    const int lane = tid & 31;
    const int g    = lane >> 2;
    const int t4   = lane & 3;
    const int r    = wid >> 3;           // 0 -> row y0, 1 -> row y0+1
    const int w8   = wid & 7;
    const int wpx  = w8 & 3;             // px quarter (64 px each)
    const int wo   = w8 >> 2;            // oc half (32 oc each)
    const int wm   = wpx * 64;           // warp's px base
    const int y0   = blockIdx.x * 2;
    const int b    = blockIdx.y;

    float acc[4][4][4];                  // [mt][nt][frag]
#pragma unroll
    for (int mt = 0; mt < 4; ++mt)
#pragma unroll
        for (int nt = 0; nt < 4; ++nt)
#pragma unroll
            for (int q = 0; q < 4; ++q) acc[mt][nt][q] = 0.f;

    // issue cp.asyncs for iteration u into slot u % NSTG, then commit.
    auto issue_stage = [&](int u) {
        const int s  = u & 31;
        const int cq = u >> 5;               // channel octet
        const uint32_t base = sbase + (uint32_t)(u % NSTG) * STAGE_B;
        for (int k = tid; k < CH * 72; k += 512) {        // rows
            const int ch = k / 72;
            const int e  = k - ch * 72;
            const char* src =
                (const char*)&g_pair[b][CH * cq + ch][y0 + s][0] + e * 16;
            CP16(base + (uint32_t)ch * ROW_B + (uint32_t)e * 16, src);
        }
        if (s < Kk) {                                     // weight slices
            for (int k = tid; k < CH * 320; k += 512) {
                const int ch = k / 320;
                const int e  = k - ch * 320;
                const char* src =
                    (const char*)&g_ws[(CH * cq + ch) * Kk + s][0] + e * 16;
                CP16(base + CH * ROW_B + (uint32_t)ch * WS_B + (uint32_t)e * 16,
                     src);
            }
        }
        CP_COMMIT();
    };

    // ---- prologue: fill pipeline with stages 0..1 ----
    issue_stage(0);
    issue_stage(1);

    for (int t = 0; t < NIT; ++t) {
        const int s = t & 31;

        CP_WAIT1();          // stage t landed (<=1 younger group outstanding)
        __syncthreads();     // visible to all; all warps done with iter t-1

        // ---- compute: CH channels x (4 mt x 4 nt x 2 kc) MMAs ----
        // group 0 (row y0):   i = s,   slot t%4      (valid s < 31)
        // group 1 (row y0+1): i = s-1, slot (t+3)%4  (valid s >= 1)
        const bool valid = r ? (s >= 1) : (s < Kk);
        if (valid) {
            const uint32_t roff = (uint32_t)(t % NSTG) * STAGE_B;
            const uint32_t wsl  = r ? ((t + 3) % NSTG) : (t % NSTG);
            const uint32_t woff = wsl * STAGE_B + CH * ROW_B;
#pragma unroll
            for (int ch = 0; ch < CH; ++ch) {
                const uint32_t* rp = (const uint32_t*)(dsm + roff + ch * ROW_B);
                const __half*   wb = (const __half*)(dsm + woff + ch * WS_B);
                // A Toeplitz pair-loads: cover 64 px + 31 taps (11 words)
                const int abase = wm + g + 2 * t4;
                uint32_t p[11];
#pragma unroll
                for (int z = 0; z < 11; ++z) p[z] = rp[abase + 8 * z];
                // B fragments for this warp's 32-oc half
                uint32_t bf[4][4];   // [nt][b00,b01,b10,b11]
#pragma unroll
                for (int nt = 0; nt < 4; ++nt) {
                    const uint32_t* wrow =
                        (const uint32_t*)(wb + (wo * 32 + nt * 8 + g) * WSP) + t4;
                    bf[nt][0] = wrow[0];
                    bf[nt][1] = wrow[4];
                    bf[nt][2] = wrow[8];
                    bf[nt][3] = wrow[12];
                }
#pragma unroll
                for (int mt = 0; mt < 4; ++mt) {
                    // kc=0: taps 0-15 ; kc=1: taps 16-31 (z base = 2*mt)
                    uint32_t a0[4] = {p[2 * mt],     p[2 * mt + 1],
                                      p[2 * mt + 1], p[2 * mt + 2]};
                    uint32_t a1[4] = {p[2 * mt + 2], p[2 * mt + 3],
                                      p[2 * mt + 3], p[2 * mt + 4]};
#pragma unroll
                    for (int nt = 0; nt < 4; ++nt) {
                        MMA16816(acc[mt][nt], a0, bf[nt][0], bf[nt][1]);
                        MMA16816(acc[mt][nt], a1, bf[nt][2], bf[nt][3]);
                    }
                }
            }
        }

        // ---- issue stage t+2 (slot (t+2)%4; last readers ran iter t-1) ----
        if (t + 2 < NIT) issue_stage(t + 2);
        else CP_COMMIT();   // keep group count uniform for wait_group
    }

    // ---- epilogue ----
    const int yrow = y0 + r;
#pragma unroll
    for (int nt = 0; nt < 4; ++nt) {
        const int oc0 = wo * 32 + nt * 8 + 2 * t4;
        const float bv0 = bias[oc0];
        const float bv1 = bias[oc0 + 1];
        float* p0 = out + (((size_t)b * OC + oc0) * Hh + yrow) * Ww;
        float* p1 = p0 + (size_t)Hh * Ww;
#pragma unroll
        for (int mt = 0; mt < 4; ++mt) {
            const int px = wm + mt * 16 + g;
            p0[px]     = acc[mt][nt][0] + bv0;
            p1[px]     = acc[mt][nt][1] + bv1;
            p0[px + 8] = acc[mt][nt][2] + bv0;
            p1[px + 8] = acc[mt][nt][3] + bv1;
        }
    }
}

extern "C" void kernel_launch(void* const* d_in, const int* in_sizes, int n_in,
                              void* d_out, int out_size)
{
    using namespace fc;
    const float* sig  = (const float*)d_in[0];  // (8, 64, 256, 256)
    const float* wgt  = (const float*)d_in[1];  // (64, 64, 31, 31)
    const float* bias = (const float*)d_in[2];  // (64,)
    float* out = (float*)d_out;                 // (8, 64, 256, 256) fp32

    // pre-pass: build fp16 staging images (deterministic, every call)
    build_pairs<<<dim3(YPAD, Cc, 8), ROWP>>>(sig);
    build_ws<<<Cc * Kk, 256>>>(wgt);

    cudaFuncSetAttribute(fftconv_m64n32_kernel,
                         cudaFuncAttributeMaxDynamicSharedMemorySize, SMEM_BYTES);
    dim3 grid(Hh / 2, 8);   // one CTA per (2 output rows, batch)
    fftconv_m64n32_kernel<<<grid, 512, SMEM_BYTES>>>(bias, out);
}

// round 14
// speedup vs baseline: 10.9000x; 1.0001x over previous
#include <cuda_runtime.h>
#include <cuda_fp16.h>
#include <cstdint>

// FFTConv2d == direct cross-correlation:
//   out[b,o,y,x] = sum_{c,i,j} sig[b,c,y+i-15,x+j-15] * w[o,c,i,j] + bias[o]
// R12: warp tile reshaped 32px x 64oc -> 64px x 32oc (mt=4, nt=4) to cut
// redundant B-fragment LDS traffic ~30% (crossbar was co-limiting).
// Staging unchanged from R11: pre-pass fp16 images, cp.async ring-4 depth-2,
// CH=8 channels/stage, 256-MMA bursts per barrier.
// CTA = (b, y0..y0+1); warps 0-7 row y0 (i=s), warps 8-15 row y0+1 (i=s-1).

namespace fc {
constexpr int Cc = 64, OC = 64, Hh = 256, Ww = 256, Kk = 31, PD = 15;
constexpr int WSP = 40;              // ws pitch in halves (20 words)
constexpr int CH = 8;                // channels per stage
constexpr int NIT = (Cc / CH) * 32;  // 256 iterations
constexpr int NSTG = 4;              // smem ring stages
constexpr int ROWP = 288;            // half2 pairs per staged row
constexpr int YPAD = 286;            // padded input rows per (b,c)
constexpr uint32_t ROW_B   = ROWP * 4;                 // 1152
constexpr uint32_t WS_B    = 64 * WSP * 2;             // 5120
constexpr uint32_t STAGE_B = CH * ROW_B + CH * WS_B;   // 50176
constexpr uint32_t SMEM_BYTES = NSTG * STAGE_B;        // 200704
}

// ---- scratch (uninitialized __device__ globals: no allocation) ----
__device__ __half2 g_pair[8][64][fc::YPAD][fc::ROWP];     // ~169 MB
__device__ __half  g_ws[fc::Cc * fc::Kk][64 * fc::WSP];   // ~10 MB

#define MMA16816(d, a, b0v, b1v)                                            \
    asm volatile("mma.sync.aligned.m16n8k16.row.col.f32.f16.f16.f32 "       \
                 "{%0,%1,%2,%3}, {%4,%5,%6,%7}, {%8,%9}, {%0,%1,%2,%3};"    \
                 : "+f"((d)[0]), "+f"((d)[1]), "+f"((d)[2]), "+f"((d)[3])   \
                 : "r"((a)[0]), "r"((a)[1]), "r"((a)[2]), "r"((a)[3]),      \
                   "r"(b0v), "r"(b1v))

#define CP16(dst, src) \
    asm volatile("cp.async.cg.shared.global [%0], [%1], 16;" \
                 :: "r"(dst), "l"(src) : "memory")
#define CP_COMMIT() asm volatile("cp.async.commit_group;" ::: "memory")
#define CP_WAIT1()  asm volatile("cp.async.wait_group 1;" ::: "memory")

__device__ __forceinline__ uint32_t smem_u32(const void* p) {
    uint32_t a;
    asm("{ .reg .u64 t; cvta.to.shared.u64 t, %1; cvt.u32.u64 %0, t; }"
        : "=r"(a) : "l"(p));
    return a;
}

// ---- pre-pass 1: pair-duplicated fp16 rows with padding baked in ----
__global__ void build_pairs(const float* __restrict__ sig) {
    using namespace fc;
    const int q  = threadIdx.x;       // 0..287
    const int yp = blockIdx.x;        // 0..285 (yy = yp - 15)
    const int c  = blockIdx.y;
    const int b  = blockIdx.z;
    const int yy = yp - PD;
    const bool rowok = ((unsigned)yy < (unsigned)Hh);
    const float* srow = sig + (((size_t)b * Cc + c) * Hh + (rowok ? yy : 0)) * Ww;
    const int x = q - PD;
    const float f0 = (rowok && (unsigned)x < (unsigned)Ww) ? srow[x] : 0.f;
    const float f1 = (rowok && (unsigned)(x + 1) < (unsigned)Ww) ? srow[x + 1] : 0.f;
    g_pair[b][c][yp][q] = __floats2half2_rn(f0, f1);
}

// ---- pre-pass 2: weight slice smem images (64 oc x 40 halves, j>=31 = 0) ----
__global__ void build_ws(const float* __restrict__ wgt) {
    using namespace fc;
    const int ci = blockIdx.x;        // c*31 + s
    const int c  = ci / Kk;
    const int s  = ci - c * Kk;
    for (int k = threadIdx.x; k < 64 * WSP; k += blockDim.x) {
        const int oc = k / WSP;
        const int j  = k - oc * WSP;
        const float v = (j < Kk)
            ? wgt[(((size_t)oc * Cc + c) * Kk + s) * Kk + j] : 0.f;
        g_ws[ci][k] = __float2half_rn(v);
    }
}

// ---- main kernel ----
__global__ void __launch_bounds__(512, 1)
fftconv_m64n32_kernel(const float* __restrict__ bias,
                      float* __restrict__ out)
{
    using namespace fc;
    extern __shared__ __align__(16) char dsm[];
    const uint32_t sbase = smem_u32(dsm);

    const int tid  = threadIdx.x;
    const int wid  = tid >> 5;
    const int lane = tid & 31;
    const int g    = lane >> 2;
    const int t4   = lane & 3;
    const int r    = wid >> 3;           // 0 -> row y0, 1 -> row y0+1
    const int w8   = wid & 7;
    const int wpx  = w8 & 3;             // px quarter (64 px each)
    const int wo   = w8 >> 2;            // oc half (32 oc each)
    const int wm   = wpx * 64;           // warp's px base
    const int y0   = blockIdx.x * 2;
    const int b    = blockIdx.y;

    float acc[4][4][4];                  // [mt][nt][frag]
#pragma unroll
    for (int mt = 0; mt < 4; ++mt)
#pragma unroll
        for (int nt = 0; nt < 4; ++nt)
#pragma unroll
            for (int q = 0; q < 4; ++q) acc[mt][nt][q] = 0.f;

    // issue cp.asyncs for iteration u into slot u % NSTG, then commit.
    auto issue_stage = [&](int u) {
        const int s  = u & 31;
        const int cq = u >> 5;               // channel octet
        const uint32_t base = sbase + (uint32_t)(u % NSTG) * STAGE_B;
        for (int k = tid; k < CH * 72; k += 512) {        // rows
            const int ch = k / 72;
            const int e  = k - ch * 72;
            const char* src =
                (const char*)&g_pair[b][CH * cq + ch][y0 + s][0] + e * 16;
            CP16(base + (uint32_t)ch * ROW_B + (uint32_t)e * 16, src);
        }
        if (s < Kk) {                                     // weight slices
            for (int k = tid; k < CH * 320; k += 512) {
                const int ch = k / 320;
                const int e  = k - ch * 320;
                const char* src =
                    (const char*)&g_ws[(CH * cq + ch) * Kk + s][0] + e * 16;
                CP16(base + CH * ROW_B + (uint32_t)ch * WS_B + (uint32_t)e * 16,
                     src);
            }
        }
        CP_COMMIT();
    };

    // ---- prologue: fill pipeline with stages 0..1 ----
    issue_stage(0);
    issue_stage(1);

    for (int t = 0; t < NIT; ++t) {
        const int s = t & 31;

        CP_WAIT1();          // stage t landed (<=1 younger group outstanding)
        __syncthreads();     // visible to all; all warps done with iter t-1

        // ---- compute: CH channels x (4 mt x 4 nt x 2 kc) MMAs ----
        // group 0 (row y0):   i = s,   slot t%4      (valid s < 31)
        // group 1 (row y0+1): i = s-1, slot (t+3)%4  (valid s >= 1)
        const bool valid = r ? (s >= 1) : (s < Kk);
        if (valid) {
            const uint32_t roff = (uint32_t)(t % NSTG) * STAGE_B;
            const uint32_t wsl  = r ? ((t + 3) % NSTG) : (t % NSTG);
            const uint32_t woff = wsl * STAGE_B + CH * ROW_B;
#pragma unroll
            for (int ch = 0; ch < CH; ++ch) {
                const uint32_t* rp = (const uint32_t*)(dsm + roff + ch * ROW_B);
                const __half*   wb = (const __half*)(dsm + woff + ch * WS_B);
                // A Toeplitz pair-loads: cover 64 px + 31 taps (11 words)
                const int abase = wm + g + 2 * t4;
                uint32_t p[11];
#pragma unroll
                for (int z = 0; z < 11; ++z) p[z] = rp[abase + 8 * z];
                // B fragments for this warp's 32-oc half
                uint32_t bf[4][4];   // [nt][b00,b01,b10,b11]
#pragma unroll
                for (int nt = 0; nt < 4; ++nt) {
                    const uint32_t* wrow =
                        (const uint32_t*)(wb + (wo * 32 + nt * 8 + g) * WSP) + t4;
                    bf[nt][0] = wrow[0];
                    bf[nt][1] = wrow[4];
                    bf[nt][2] = wrow[8];
                    bf[nt][3] = wrow[12];
                }
#pragma unroll
                for (int mt = 0; mt < 4; ++mt) {
                    // kc=0: taps 0-15 ; kc=1: taps 16-31 (z base = 2*mt)
                    uint32_t a0[4] = {p[2 * mt],     p[2 * mt + 1],
                                      p[2 * mt + 1], p[2 * mt + 2]};
                    uint32_t a1[4] = {p[2 * mt + 2], p[2 * mt + 3],
                                      p[2 * mt + 3], p[2 * mt + 4]};
#pragma unroll
                    for (int nt = 0; nt < 4; ++nt) {
                        MMA16816(acc[mt][nt], a0, bf[nt][0], bf[nt][1]);
                        MMA16816(acc[mt][nt], a1, bf[nt][2], bf[nt][3]);
                    }
                }
            }
        }

        // ---- issue stage t+2 (slot (t+2)%4; last readers ran iter t-1) ----
        if (t + 2 < NIT) issue_stage(t + 2);
        else CP_COMMIT();   // keep group count uniform for wait_group
    }

    // ---- epilogue ----
    const int yrow = y0 + r;
#pragma unroll
    for (int nt = 0; nt < 4; ++nt) {
        const int oc0 = wo * 32 + nt * 8 + 2 * t4;
        const float bv0 = bias[oc0];
        const float bv1 = bias[oc0 + 1];
        float* p0 = out + (((size_t)b * OC + oc0) * Hh + yrow) * Ww;
        float* p1 = p0 + (size_t)Hh * Ww;
#pragma unroll
        for (int mt = 0; mt < 4; ++mt) {
            const int px = wm + mt * 16 + g;
            p0[px]     = acc[mt][nt][0] + bv0;
            p1[px]     = acc[mt][nt][1] + bv1;
            p0[px + 8] = acc[mt][nt][2] + bv0;
            p1[px + 8] = acc[mt][nt][3] + bv1;
        }
    }
}

extern "C" void kernel_launch(void* const* d_in, const int* in_sizes, int n_in,
                              void* d_out, int out_size)
{
    using namespace fc;
    const float* sig  = (const float*)d_in[0];  // (8, 64, 256, 256)
    const float* wgt  = (const float*)d_in[1];  // (64, 64, 31, 31)
    const float* bias = (const float*)d_in[2];  // (64,)
    float* out = (float*)d_out;                 // (8, 64, 256, 256) fp32

    // pre-pass: build fp16 staging images (deterministic, every call)
    build_pairs<<<dim3(YPAD, Cc, 8), ROWP>>>(sig);
    build_ws<<<Cc * Kk, 256>>>(wgt);

    cudaFuncSetAttribute(fftconv_m64n32_kernel,
                         cudaFuncAttributeMaxDynamicSharedMemorySize, SMEM_BYTES);
    dim3 grid(Hh / 2, 8);   // one CTA per (2 output rows, batch)
    fftconv_m64n32_kernel<<<grid, 512, SMEM_BYTES>>>(bias, out);
}

// round 15
// speedup vs baseline: 63.8701x; 5.8596x over previous
#include <cuda_runtime.h>
#include <cuda_fp16.h>
#include <cstdint>
#include <math.h>

// FFTConv2d via row-DFT (length 288, no wrap). 6 kernels:
// K1 fwd-DFT matrix, K2 S_f=sig*DFT, K3 W_f packed conj, K4 main GEMM
// P=Toeplitz(S_f)*B1 per (b,f), K5 IDFT matrix hi/lo, K6 out=P*IDFT+bias.
namespace fc {
constexpr int Bn=8, Cc=64, Oc=64, Hh=256, Ww=256, Kk=31, PD=15;
constexpr int Nd=288, Fb=145, FP=160;
constexpr float TPN = 6.283185307179586f/288.0f;
}
__device__ __half2 g_DS[320*132];
__device__ __half2 g_S [(size_t)8*160*64*288];
__device__ __half2 g_B1[(size_t)145*64*128*36];
__device__ __half2 g_O [(size_t)8*64*256*148];
__device__ __half2 g_B2[2*19*256*12];

#define MMA16816(d,a,b0v,b1v) \
    asm volatile("mma.sync.aligned.m16n8k16.row.col.f32.f16.f16.f32 " \
        "{%0,%1,%2,%3}, {%4,%5,%6,%7}, {%8,%9}, {%0,%1,%2,%3};" \
        : "+f"((d)[0]),"+f"((d)[1]),"+f"((d)[2]),"+f"((d)[3]) \
        : "r"((a)[0]),"r"((a)[1]),"r"((a)[2]),"r"((a)[3]),"r"(b0v),"r"(b1v))
#define CP16(dst,src) asm volatile("cp.async.cg.shared.global [%0], [%1], 16;" \
    :: "r"(dst),"l"(src):"memory")
#define CP4(dst,src) asm volatile("cp.async.ca.shared.global [%0], [%1], 4;" \
    :: "r"(dst),"l"(src):"memory")
#define CP_COMMIT() asm volatile("cp.async.commit_group;":::"memory")
#define CP_WAIT(n)  asm volatile("cp.async.wait_group %0;"::"n"(n):"memory")

__device__ __forceinline__ uint32_t smem_u32(const void* p){
    uint32_t a;
    asm("{ .reg .u64 t; cvta.to.shared.u64 t, %1; cvt.u32.u64 %0, t; }":"=r"(a):"l"(p));
    return a;
}
__device__ __forceinline__ void sc288(int m, float& s, float& c){
    sincosf(fc::TPN*(float)m, &s, &c);
}

// K1: fwd DFT image: col n=2f+ri, word w = x-pair (2w,2w+1), phase -(x+15)f
__global__ void k1_DS(){
    using namespace fc;
    const int n=blockIdx.x, w=threadIdx.x, f=n>>1, ri=n&1;
    float v0=0.f, v1=0.f;
    if(w<128 && f<Fb){
        float s,c;
        sc288((f*(2*w+15))%Nd,s,c); v0 = ri? -s : c;
        sc288((f*(2*w+16))%Nd,s,c); v1 = ri? -s : c;
    }
    g_DS[n*132+w]=__floats2half2_rn(v0,v1);
}

// K2: S_f[b][f][c][yy] GEMM, grid(3,64,8): M=96 yy, N=320, K=256
__global__ void __launch_bounds__(512,1) k2_fwd(const float* __restrict__ sig){
    using namespace fc;
    extern __shared__ __align__(16) char dsm[];
    const uint32_t sb=smem_u32(dsm), B_OFF=96*132*4;
    const int tid=threadIdx.x, wid=tid>>5, lane=tid&31, g=lane>>2, t4=lane&3;
    const int m3=blockIdx.x, c=blockIdx.y, b=blockIdx.z;
    const int wm2=(wid>>3)*48, wn=(wid&7)*40;
    for(int idx=tid; idx<320*132/4; idx+=512)
        CP16(sb+B_OFF+idx*16, (const char*)g_DS+idx*16);
    CP_COMMIT();
    __half2* As=(__half2*)dsm;
    const float* s0=sig+((size_t)b*Cc+c)*Hh*Ww;
    for(int idx=tid; idx<96*132; idx+=512){
        const int r=idx/132, w=idx-r*132, ys=m3*96+r-PD;
        __half2 h=__floats2half2_rn(0.f,0.f);
        if(w<128 && (unsigned)ys<(unsigned)Hh){
            const float2 v=*(const float2*)(s0+(size_t)ys*Ww+2*w);
            h=__floats2half2_rn(v.x,v.y);
        }
        As[idx]=h;
    }
    CP_WAIT(0); __syncthreads();
    float acc[3][5][4];
#pragma unroll
    for(int mt=0;mt<3;++mt)
#pragma unroll
        for(int nt=0;nt<5;++nt)
#pragma unroll
            for(int q=0;q<4;++q) acc[mt][nt][q]=0.f;
    const uint32_t* Aw=(const uint32_t*)dsm;
    const uint32_t* Bw=(const uint32_t*)(dsm+B_OFF);
#pragma unroll
    for(int ks=0;ks<16;++ks){
        uint32_t bf[5][2];
#pragma unroll
        for(int nt=0;nt<5;++nt){
            const int col=wn+nt*8+g;
            bf[nt][0]=Bw[col*132+8*ks+t4];
            bf[nt][1]=Bw[col*132+8*ks+4+t4];
        }
#pragma unroll
        for(int mt=0;mt<3;++mt){
            const int row=wm2+mt*16+g;
            uint32_t a[4];
            a[0]=Aw[row*132+8*ks+t4];     a[1]=Aw[(row+8)*132+8*ks+t4];
            a[2]=Aw[row*132+8*ks+4+t4];   a[3]=Aw[(row+8)*132+8*ks+4+t4];
#pragma unroll
            for(int nt=0;nt<5;++nt) MMA16816(acc[mt][nt],a,bf[nt][0],bf[nt][1]);
        }
    }
#pragma unroll
    for(int nt=0;nt<5;++nt){
        const int f=(wn+nt*8)/2+t4;
#pragma unroll
        for(int mt=0;mt<3;++mt){
            const int yy=m3*96+wm2+mt*16+g;
            const size_t base=(((size_t)b*FP+f)*Cc+c)*288;
            g_S[base+yy]  =__floats2half2_rn(acc[mt][nt][0],acc[mt][nt][1]);
            g_S[base+yy+8]=__floats2half2_rn(acc[mt][nt][2],acc[mt][nt][3]);
        }
    }
}

// K3: W_f fp32 -> packed conj B1[f][c][2o|2o+1][36]
__global__ void k3_B1(const float* __restrict__ wgt){
    using namespace fc;
    __shared__ float wsm[961];
    const int o=blockIdx.x, c=blockIdx.y, f=threadIdx.x;
    for(int idx=threadIdx.x; idx<961; idx+=160)
        wsm[idx]=wgt[((size_t)(o*Cc+c))*961+idx];
    __syncthreads();
    if(f>=Fb) return;
    float wr[31], wi[31];
#pragma unroll
    for(int i=0;i<31;++i){ wr[i]=0.f; wi[i]=0.f; }
    for(int j=0;j<31;++j){
        float s,cv; sc288((f*j)%Nd,s,cv);
#pragma unroll
        for(int i=0;i<31;++i){
            const float v=wsm[i*31+j];
            wr[i]+=v*cv; wi[i]-=v*s;
        }
    }
    const size_t base=(((size_t)f*Cc+c)*128+2*o)*36;
    for(int w=0;w<36;++w){
        const float r=(w<31)?wr[w]:0.f, m=(w<31)?wi[w]:0.f;
        g_B1[base+w]   =__floats2half2_rn(r,m);
        g_B1[base+36+w]=__floats2half2_rn(-m,r);
    }
}

// K4: per (b,f): P[y][2o+ri] = Toeplitz(S_f) x B1. M=256,N=128,K=64c*64h
__global__ void __launch_bounds__(512,1) k4_gemm1(){
    using namespace fc;
    extern __shared__ __align__(16) char dsm[];
    const uint32_t sb=smem_u32(dsm), B_OFF=64*288*4;
    const int tid=threadIdx.x, wid=tid>>5, lane=tid&31, g=lane>>2, t4=lane&3;
    const int wm=(wid&3)*64, wo=(wid>>2)*32;
    const int b=blockIdx.x, f=blockIdx.y;
    float acc[4][4][4];
#pragma unroll
    for(int mt=0;mt<4;++mt)
#pragma unroll
        for(int nt=0;nt<4;++nt)
#pragma unroll
            for(int q=0;q<4;++q) acc[mt][nt][q]=0.f;
    const size_t sbase=(((size_t)b*FP+f)*Cc)*288;
    const size_t bbase=((size_t)f*Cc)*128*36;
    auto stageB=[&](int c){
        const uint32_t dst=sb+B_OFF+(uint32_t)(c&3)*18432u;
        const char* src=(const char*)(g_B1+bbase+(size_t)c*4608);
        for(int idx=tid; idx<1152; idx+=512) CP16(dst+idx*16, src+idx*16);
        CP_COMMIT();
    };
    {
        const char* src=(const char*)(g_S+sbase);
        for(int idx=tid; idx<4608; idx+=512) CP16(sb+idx*16, src+idx*16);
    }
    stageB(0); stageB(1); stageB(2);
    const uint32_t* Aw=(const uint32_t*)dsm;
    for(int c=0;c<Cc;++c){
        CP_WAIT(2); __syncthreads();
        const uint32_t* Bw=(const uint32_t*)(dsm+B_OFF+(uint32_t)(c&3)*18432u);
        const int base=c*288+wm+g+t4;
        uint32_t p[22];
#pragma unroll
        for(int z=0;z<22;++z) p[z]=Aw[base+4*z];
#pragma unroll
        for(int ks=0;ks<4;++ks){
            uint32_t bf[4][2];
#pragma unroll
            for(int nt=0;nt<4;++nt){
                const int col=wo+nt*8+g;
                bf[nt][0]=Bw[col*36+8*ks+t4];
                bf[nt][1]=Bw[col*36+8*ks+4+t4];
            }
#pragma unroll
            for(int mt=0;mt<4;++mt){
                const int q=4*mt+2*ks;
                uint32_t a[4]={p[q],p[q+2],p[q+1],p[q+3]};
#pragma unroll
                for(int nt=0;nt<4;++nt) MMA16816(acc[mt][nt],a,bf[nt][0],bf[nt][1]);
            }
        }
        if(c+3<Cc) stageB(c+3); else CP_COMMIT();
    }
#pragma unroll
    for(int nt=0;nt<4;++nt){
        const int o=(wo+nt*8+2*t4)>>1;
#pragma unroll
        for(int mt=0;mt<4;++mt){
            const int y=wm+mt*16+g;
            const size_t base=(((size_t)b*Oc+o)*Hh+y)*148+f;
            g_O[base]      =__floats2half2_rn(acc[mt][nt][0],acc[mt][nt][1]);
            g_O[base+8*148]=__floats2half2_rn(acc[mt][nt][2],acc[mt][nt][3]);
        }
    }
}

// K5: IDFT matrix hi/lo: word w -> f=8ks+w: (cf*cos(2pi f x/288), -cf*sin)
__global__ void k5_B2(){
    using namespace fc;
    const int ks=blockIdx.x, x=blockIdx.y, tid=threadIdx.x;
    const int h=tid/12, w=tid-h*12, fq=ks*8+w;
    float re=0.f, im=0.f;
    if(w<8 && fq<Fb){
        const float cf=(fq==0||fq==144)?1.f:2.f;
        float s,c; sc288((fq*x)%Nd,s,c);
        re=cf*c; im=-cf*s;
    }
    const __half rh=__float2half_rn(re), mh=__float2half_rn(im);
    __half2 o;
    if(h==0) o=__halves2half2(rh,mh);
    else o=__floats2half2_rn(re-__half2float(rh), im-__half2float(mh));
    g_B2[((h*19+ks)*256+x)*12+w]=o;
}

// K6: out = P x IDFT(hi+lo) /288 + bias. grid(o,b,yh): M=128,N=256,K=2x19ks
__global__ void __launch_bounds__(512,1)
k6_gemm2(const float* __restrict__ bias, float* __restrict__ out){
    using namespace fc;
    extern __shared__ __align__(16) char dsm[];
    const uint32_t sb=smem_u32(dsm), B_OFF=128*164*4;
    const int tid=threadIdx.x, wid=tid>>5, lane=tid&31, g=lane>>2, t4=lane&3;
    const int wm=(wid>>2)*32, wn=(wid&3)*64;
    const int o=blockIdx.x, b=blockIdx.y, yh=blockIdx.z;
    float acc[2][8][4];
#pragma unroll
    for(int mt=0;mt<2;++mt)
#pragma unroll
        for(int nt=0;nt<8;++nt)
#pragma unroll
            for(int q=0;q<4;++q) acc[mt][nt][q]=0.f;
    auto stageB=[&](int u){
        const uint32_t dst=sb+B_OFF+(uint32_t)(u&3)*12288u;
        const char* src=(const char*)(g_B2+(size_t)u*256*12);
        for(int idx=tid; idx<768; idx+=512) CP16(dst+idx*16, src+idx*16);
        CP_COMMIT();
    };
    {
        const char* ab=(const char*)(g_O+(((size_t)b*Oc+o)*Hh+yh*128)*148);
        for(int idx=tid; idx<128*37; idx+=512){
            const int r=idx/37, e=idx-r*37;
            if(e<36) CP16(sb+r*656+e*16, ab+(size_t)r*592+e*16);
            else     CP4(sb+r*656+576, ab+(size_t)r*592+576);
        }
        __half2* As=(__half2*)dsm;
        for(int idx=tid; idx<128*19; idx+=512){
            const int r=idx/19, e=idx-r*19;
            As[r*164+145+e]=__floats2half2_rn(0.f,0.f);
        }
    }
    stageB(0); stageB(1);
    const uint32_t* Aw=(const uint32_t*)dsm;
    for(int u=0;u<38;++u){
        const int ks=(u<19)?u:u-19;
        CP_WAIT(1); __syncthreads();
        const uint32_t* Bw=(const uint32_t*)(dsm+B_OFF+(uint32_t)(u&3)*12288u);
        uint32_t bf[8][2];
#pragma unroll
        for(int nt=0;nt<8;++nt){
            const int col=wn+nt*8+g;
            bf[nt][0]=Bw[col*12+t4];
            bf[nt][1]=Bw[col*12+4+t4];
        }
#pragma unroll
        for(int mt=0;mt<2;++mt){
            const int row=wm+mt*16+g;
            uint32_t a[4];
            a[0]=Aw[row*164+8*ks+t4];     a[1]=Aw[(row+8)*164+8*ks+t4];
            a[2]=Aw[row*164+8*ks+4+t4];   a[3]=Aw[(row+8)*164+8*ks+4+t4];
#pragma unroll
            for(int nt=0;nt<8;++nt) MMA16816(acc[mt][nt],a,bf[nt][0],bf[nt][1]);
        }
        if(u+2<38) stageB(u+2); else CP_COMMIT();
    }
    const float inv=1.0f/288.0f, bv=bias[o];
    float* op=out+(((size_t)b*Oc+o)*Hh+yh*128)*Ww;
#pragma unroll
    for(int nt=0;nt<8;++nt){
        const int x0=wn+nt*8+2*t4;
#pragma unroll
        for(int mt=0;mt<2;++mt){
            const int y=wm+mt*16+g;
            float2 v0={acc[mt][nt][0]*inv+bv, acc[mt][nt][1]*inv+bv};
            float2 v1={acc[mt][nt][2]*inv+bv, acc[mt][nt][3]*inv+bv};
            *(float2*)(op+(size_t)y*Ww+x0)=v0;
            *(float2*)(op+(size_t)(y+8)*Ww+x0)=v1;
        }
    }
}

extern "C" void kernel_launch(void* const* d_in, const int* in_sizes, int n_in,
                              void* d_out, int out_size)
{
    using namespace fc;
    const float* sig =(const float*)d_in[0];
    const float* wgt =(const float*)d_in[1];
    const float* bias=(const float*)d_in[2];
    float* out=(float*)d_out;

    cudaFuncSetAttribute(k2_fwd,  cudaFuncAttributeMaxDynamicSharedMemorySize, 219648);
    cudaFuncSetAttribute(k4_gemm1,cudaFuncAttributeMaxDynamicSharedMemorySize, 147456);
    cudaFuncSetAttribute(k6_gemm2,cudaFuncAttributeMaxDynamicSharedMemorySize, 133120);

    k1_DS<<<320, 132>>>();
    k3_B1<<<dim3(Oc, Cc), 160>>>(wgt);
    k5_B2<<<dim3(19, 256), 24>>>();
    k2_fwd<<<dim3(3, Cc, Bn), 512, 219648>>>(sig);
    k4_gemm1<<<dim3(Bn, Fb), 512, 147456>>>();
    k6_gemm2<<<dim3(Oc, Bn, 2), 512, 133120>>>(bias, out);
}

// round 16
// speedup vs baseline: 67.9941x; 1.0646x over previous
#include <cuda_runtime.h>
#include <cuda_fp16.h>
#include <cstdint>
#include <math.h>

// FFTConv2d via row-DFT (len 288). K1 DFT mat; K2 S_f=sig*DFT; K2b A-variant
// pair images (Sp=Sr+Si, Sr, Si); K3 W_f -> 3 Karatsuba B cols (Wr, Wr+Wi,
// Wr-Wi); K4 3-mult complex GEMM P (Re=m1-m3, Im=m1-m2); K5 IDFT hi/lo;
// K6 out = P*IDFT/288 + bias.
namespace fc {
constexpr int Bn=8, Cc=64, Oc=64, Hh=256, Ww=256, Kk=31, PD=15;
constexpr int Nd=288, Fb=145, FP=160;
constexpr float TPN = 6.283185307179586f/288.0f;
}
__device__ __half2 g_DS[320*132];
__device__ __half2 g_S [(size_t)8*160*64*288];
__device__ __half2 g_A [(size_t)8*145*64*3*288];     // pair-dup A variants
__device__ __half2 g_B1[(size_t)145*64*64*3*20];     // [f][c][o][term][20w]
__device__ __half2 g_O [(size_t)8*64*256*148];
__device__ __half2 g_B2[2*19*256*12];

#define MMA16816(d,a,b0v,b1v) \
    asm volatile("mma.sync.aligned.m16n8k16.row.col.f32.f16.f16.f32 " \
        "{%0,%1,%2,%3}, {%4,%5,%6,%7}, {%8,%9}, {%0,%1,%2,%3};" \
        : "+f"((d)[0]),"+f"((d)[1]),"+f"((d)[2]),"+f"((d)[3]) \
        : "r"((a)[0]),"r"((a)[1]),"r"((a)[2]),"r"((a)[3]),"r"(b0v),"r"(b1v))
#define CP16(dst,src) asm volatile("cp.async.cg.shared.global [%0], [%1], 16;" \
    :: "r"(dst),"l"(src):"memory")
#define CP4(dst,src) asm volatile("cp.async.ca.shared.global [%0], [%1], 4;" \
    :: "r"(dst),"l"(src):"memory")
#define CP_COMMIT() asm volatile("cp.async.commit_group;":::"memory")
#define CP_WAIT(n)  asm volatile("cp.async.wait_group %0;"::"n"(n):"memory")

__device__ __forceinline__ uint32_t smem_u32(const void* p){
    uint32_t a;
    asm("{ .reg .u64 t; cvta.to.shared.u64 t, %1; cvt.u32.u64 %0, t; }":"=r"(a):"l"(p));
    return a;
}
__device__ __forceinline__ void sc288(int m, float& s, float& c){
    sincosf(fc::TPN*(float)m, &s, &c);
}

// K1: fwd DFT image
__global__ void k1_DS(){
    using namespace fc;
    const int n=blockIdx.x, w=threadIdx.x, f=n>>1, ri=n&1;
    float v0=0.f, v1=0.f;
    if(w<128 && f<Fb){
        float s,c;
        sc288((f*(2*w+15))%Nd,s,c); v0 = ri? -s : c;
        sc288((f*(2*w+16))%Nd,s,c); v1 = ri? -s : c;
    }
    g_DS[n*132+w]=__floats2half2_rn(v0,v1);
}

// K2: S_f[b][f][c][yy] GEMM, grid(3,64,8)
__global__ void __launch_bounds__(512,1) k2_fwd(const float* __restrict__ sig){
    using namespace fc;
    extern __shared__ __align__(16) char dsm[];
    const uint32_t sb=smem_u32(dsm), B_OFF=96*132*4;
    const int tid=threadIdx.x, wid=tid>>5, lane=tid&31, g=lane>>2, t4=lane&3;
    const int m3=blockIdx.x, c=blockIdx.y, b=blockIdx.z;
    const int wm2=(wid>>3)*48, wn=(wid&7)*40;
    for(int idx=tid; idx<320*132/4; idx+=512)
        CP16(sb+B_OFF+idx*16, (const char*)g_DS+idx*16);
    CP_COMMIT();
    __half2* As=(__half2*)dsm;
    const float* s0=sig+((size_t)b*Cc+c)*Hh*Ww;
    for(int idx=tid; idx<96*132; idx+=512){
        const int r=idx/132, w=idx-r*132, ys=m3*96+r-PD;
        __half2 h=__floats2half2_rn(0.f,0.f);
        if(w<128 && (unsigned)ys<(unsigned)Hh){
            const float2 v=*(const float2*)(s0+(size_t)ys*Ww+2*w);
            h=__floats2half2_rn(v.x,v.y);
        }
        As[idx]=h;
    }
    CP_WAIT(0); __syncthreads();
    float acc[3][5][4];
#pragma unroll
    for(int mt=0;mt<3;++mt)
#pragma unroll
        for(int nt=0;nt<5;++nt)
#pragma unroll
            for(int q=0;q<4;++q) acc[mt][nt][q]=0.f;
    const uint32_t* Aw=(const uint32_t*)dsm;
    const uint32_t* Bw=(const uint32_t*)(dsm+B_OFF);
#pragma unroll
    for(int ks=0;ks<16;++ks){
        uint32_t bf[5][2];
#pragma unroll
        for(int nt=0;nt<5;++nt){
            const int col=wn+nt*8+g;
            bf[nt][0]=Bw[col*132+8*ks+t4];
            bf[nt][1]=Bw[col*132+8*ks+4+t4];
        }
#pragma unroll
        for(int mt=0;mt<3;++mt){
            const int row=wm2+mt*16+g;
            uint32_t a[4];
            a[0]=Aw[row*132+8*ks+t4];     a[1]=Aw[(row+8)*132+8*ks+t4];
            a[2]=Aw[row*132+8*ks+4+t4];   a[3]=Aw[(row+8)*132+8*ks+4+t4];
#pragma unroll
            for(int nt=0;nt<5;++nt) MMA16816(acc[mt][nt],a,bf[nt][0],bf[nt][1]);
        }
    }
#pragma unroll
    for(int nt=0;nt<5;++nt){
        const int f=(wn+nt*8)/2+t4;
#pragma unroll
        for(int mt=0;mt<3;++mt){
            const int yy=m3*96+wm2+mt*16+g;
            const size_t base=(((size_t)b*FP+f)*Cc+c)*288;
            g_S[base+yy]  =__floats2half2_rn(acc[mt][nt][0],acc[mt][nt][1]);
            g_S[base+yy+8]=__floats2half2_rn(acc[mt][nt][2],acc[mt][nt][3]);
        }
    }
}

// K2b: pair-duplicated A variants: var0=Sp=Sr+Si, var1=Sr, var2=Si
__global__ void k2b_A(){
    using namespace fc;
    const int c=blockIdx.x, f=blockIdx.y, b=blockIdx.z, q=threadIdx.x;
    const size_t sbase=(((size_t)b*FP+f)*Cc+c)*288;
    const float2 v0=__half22float2(g_S[sbase+q]);
    float2 v1=make_float2(0.f,0.f);
    if(q<287) v1=__half22float2(g_S[sbase+q+1]);
    const size_t ab=((((size_t)b*Fb+f)*Cc+c)*3)*288;
    g_A[ab+q]      =__floats2half2_rn(v0.x+v0.y, v1.x+v1.y);
    g_A[ab+288+q]  =__floats2half2_rn(v0.x, v1.x);
    g_A[ab+576+q]  =__floats2half2_rn(v0.y, v1.y);
}

// K3: W_f -> g_B1[f][c][o][term][20w]; term0=Wr, term1=Wr+Wi, term2=Wr-Wi
__global__ void k3_B1(const float* __restrict__ wgt){
    using namespace fc;
    __shared__ float wsm[961];
    const int o=blockIdx.x, c=blockIdx.y, f=threadIdx.x;
    for(int idx=threadIdx.x; idx<961; idx+=160)
        wsm[idx]=wgt[((size_t)(o*Cc+c))*961+idx];
    __syncthreads();
    if(f>=Fb) return;
    float wr[31], wi[31];
#pragma unroll
    for(int i=0;i<31;++i){ wr[i]=0.f; wi[i]=0.f; }
    for(int j=0;j<31;++j){
        float s,cv; sc288((f*j)%Nd,s,cv);
#pragma unroll
        for(int i=0;i<31;++i){
            const float v=wsm[i*31+j];
            wr[i]+=v*cv; wi[i]-=v*s;
        }
    }
    const size_t base=(((size_t)f*Cc+c)*64+o)*60;
    for(int w=0;w<20;++w){
        const int t0=2*w, t1=2*w+1;
        const float r0=(t0<31)?wr[t0]:0.f, r1=(t1<31)?wr[t1]:0.f;
        const float i0=(t0<31)?wi[t0]:0.f, i1=(t1<31)?wi[t1]:0.f;
        g_B1[base+w]   =__floats2half2_rn(r0, r1);
        g_B1[base+20+w]=__floats2half2_rn(r0+i0, r1+i1);
        g_B1[base+40+w]=__floats2half2_rn(r0-i0, r1-i1);
    }
}

// K4: Karatsuba GEMM. grid(b,f,oh). M=256y, 32o x 3 terms, K=64c x 32taps.
__global__ void __launch_bounds__(512,1) k4_gemm1(){
    using namespace fc;
    extern __shared__ __align__(16) char dsm[];
    const uint32_t sb=smem_u32(dsm);
    const int tid=threadIdx.x, wid=tid>>5, lane=tid&31, g=lane>>2, t4=lane&3;
    const int wm=(wid&3)*64, wn=wid>>2;      // 4 m-warps x 4 n-warps
    const int b=blockIdx.x, f=blockIdx.y, oh=blockIdx.z;
    float acc[4][3][4];
#pragma unroll
    for(int mt=0;mt<4;++mt)
#pragma unroll
        for(int tm=0;tm<3;++tm)
#pragma unroll
            for(int q=0;q<4;++q) acc[mt][tm][q]=0.f;
    const size_t abase=((((size_t)b*Fb+f)*Cc)*3)*288;       // words per c: 864
    const size_t bbase=(((size_t)f*Cc)*64 + oh*32)*60;      // per c: +64*60
    // stage: [ch][A 3456B | B 7680B], ring 4, 2 ch per stage
    auto issue=[&](int u){
        const uint32_t base=sb+(uint32_t)(u&3)*22272u;
#pragma unroll
        for(int ch=0; ch<2; ++ch){
            const int c=2*u+ch;
            const char* asrc=(const char*)(g_A+abase+(size_t)c*864);
            const char* bsrc=(const char*)(g_B1+bbase+(size_t)c*64*60);
            const uint32_t d0=base+(uint32_t)ch*11136u;
            for(int k=tid; k<696; k+=512){
                if(k<216) CP16(d0+k*16, asrc+k*16);
                else      CP16(d0+3456+(k-216)*16, bsrc+(size_t)(k-216)*16);
            }
        }
        CP_COMMIT();
    };
    issue(0); issue(1);
    for(int u=0; u<32; ++u){
        CP_WAIT(1); __syncthreads();
        const uint32_t soff=(uint32_t)(u&3)*22272u;
#pragma unroll
        for(int ch=0; ch<2; ++ch){
            const uint32_t* rp=(const uint32_t*)(dsm+soff+ch*11136u);
            const uint32_t* wbw=(const uint32_t*)(dsm+soff+ch*11136u+3456u);
            uint32_t p[3][11];
#pragma unroll
            for(int v=0;v<3;++v)
#pragma unroll
                for(int z=0;z<11;++z) p[v][z]=rp[v*288+wm+g+2*t4+8*z];
#pragma unroll
            for(int tm=0;tm<3;++tm){
                const int cb=(wn*8+g)*60+tm*20;
                const uint32_t b00=wbw[cb+t4],   b01=wbw[cb+4+t4];
                const uint32_t b10=wbw[cb+8+t4], b11=wbw[cb+12+t4];
#pragma unroll
                for(int mt=0;mt<4;++mt){
                    uint32_t a0[4]={p[tm][2*mt],  p[tm][2*mt+1],
                                    p[tm][2*mt+1],p[tm][2*mt+2]};
                    uint32_t a1[4]={p[tm][2*mt+2],p[tm][2*mt+3],
                                    p[tm][2*mt+3],p[tm][2*mt+4]};
                    MMA16816(acc[mt][tm],a0,b00,b01);
                    MMA16816(acc[mt][tm],a1,b10,b11);
                }
            }
        }
        if(u+2<32) issue(u+2); else CP_COMMIT();
    }
    // epilogue: Re=m1-m3, Im=m1-m2; terms: 0=m1, 1=m2, 2=m3
    const int o0=oh*32+wn*8+2*t4;
#pragma unroll
    for(int mt=0;mt<4;++mt){
        const int y=wm+mt*16+g;
        const size_t e0=(((size_t)b*Oc+o0)*Hh+y)*148+f;
        const size_t e1=e0+(size_t)Hh*148;
        g_O[e0]      =__floats2half2_rn(acc[mt][0][0]-acc[mt][2][0],
                                        acc[mt][0][0]-acc[mt][1][0]);
        g_O[e0+8*148]=__floats2half2_rn(acc[mt][0][2]-acc[mt][2][2],
                                        acc[mt][0][2]-acc[mt][1][2]);
        g_O[e1]      =__floats2half2_rn(acc[mt][0][1]-acc[mt][2][1],
                                        acc[mt][0][1]-acc[mt][1][1]);
        g_O[e1+8*148]=__floats2half2_rn(acc[mt][0][3]-acc[mt][2][3],
                                        acc[mt][0][3]-acc[mt][1][3]);
    }
}

// K5: IDFT matrix hi/lo
__global__ void k5_B2(){
    using namespace fc;
    const int ks=blockIdx.x, x=blockIdx.y, tid=threadIdx.x;
    const int h=tid/12, w=tid-h*12, fq=ks*8+w;
    float re=0.f, im=0.f;
    if(w<8 && fq<Fb){
        const float cf=(fq==0||fq==144)?1.f:2.f;
        float s,c; sc288((fq*x)%Nd,s,c);
        re=cf*c; im=-cf*s;
    }
    const __half rh=__float2half_rn(re), mh=__float2half_rn(im);
    __half2 o;
    if(h==0) o=__halves2half2(rh,mh);
    else o=__floats2half2_rn(re-__half2float(rh), im-__half2float(mh));
    g_B2[((h*19+ks)*256+x)*12+w]=o;
}

// K6: out = P x IDFT(hi+lo)/288 + bias
__global__ void __launch_bounds__(512,1)
k6_gemm2(const float* __restrict__ bias, float* __restrict__ out){
    using namespace fc;
    extern __shared__ __align__(16) char dsm[];
    const uint32_t sb=smem_u32(dsm), B_OFF=128*164*4;
    const int tid=threadIdx.x, wid=tid>>5, lane=tid&31, g=lane>>2, t4=lane&3;
    const int wm=(wid>>2)*32, wn=(wid&3)*64;
    const int o=blockIdx.x, b=blockIdx.y, yh=blockIdx.z;
    float acc[2][8][4];
#pragma unroll
    for(int mt=0;mt<2;++mt)
#pragma unroll
        for(int nt=0;nt<8;++nt)
#pragma unroll
            for(int q=0;q<4;++q) acc[mt][nt][q]=0.f;
    auto stageB=[&](int u){
        const uint32_t dst=sb+B_OFF+(uint32_t)(u&3)*12288u;
        const char* src=(const char*)(g_B2+(size_t)u*256*12);
        for(int idx=tid; idx<768; idx+=512) CP16(dst+idx*16, src+idx*16);
        CP_COMMIT();
    };
    {
        const char* ab=(const char*)(g_O+(((size_t)b*Oc+o)*Hh+yh*128)*148);
        for(int idx=tid; idx<128*37; idx+=512){
            const int r=idx/37, e=idx-r*37;
            if(e<36) CP16(sb+r*656+e*16, ab+(size_t)r*592+e*16);
            else     CP4(sb+r*656+576, ab+(size_t)r*592+576);
        }
        __half2* As=(__half2*)dsm;
        for(int idx=tid; idx<128*19; idx+=512){
            const int r=idx/19, e=idx-r*19;
            As[r*164+145+e]=__floats2half2_rn(0.f,0.f);
        }
    }
    stageB(0); stageB(1);
    const uint32_t* Aw=(const uint32_t*)dsm;
    for(int u=0;u<38;++u){
        const int ks=(u<19)?u:u-19;
        CP_WAIT(1); __syncthreads();
        const uint32_t* Bw=(const uint32_t*)(dsm+B_OFF+(uint32_t)(u&3)*12288u);
        uint32_t bf[8][2];
#pragma unroll
        for(int nt=0;nt<8;++nt){
            const int col=wn+nt*8+g;
            bf[nt][0]=Bw[col*12+t4];
            bf[nt][1]=Bw[col*12+4+t4];
        }
#pragma unroll
        for(int mt=0;mt<2;++mt){
            const int row=wm+mt*16+g;
            uint32_t a[4];
            a[0]=Aw[row*164+8*ks+t4];     a[1]=Aw[(row+8)*164+8*ks+t4];
            a[2]=Aw[row*164+8*ks+4+t4];   a[3]=Aw[(row+8)*164+8*ks+4+t4];
#pragma unroll
            for(int nt=0;nt<8;++nt) MMA16816(acc[mt][nt],a,bf[nt][0],bf[nt][1]);
        }
        if(u+2<38) stageB(u+2); else CP_COMMIT();
    }
    const float inv=1.0f/288.0f, bv=bias[o];
    float* op=out+(((size_t)b*Oc+o)*Hh+yh*128)*Ww;
#pragma unroll
    for(int nt=0;nt<8;++nt){
        const int x0=wn+nt*8+2*t4;
#pragma unroll
        for(int mt=0;mt<2;++mt){
            const int y=wm+mt*16+g;
            float2 v0={acc[mt][nt][0]*inv+bv, acc[mt][nt][1]*inv+bv};
            float2 v1={acc[mt][nt][2]*inv+bv, acc[mt][nt][3]*inv+bv};
            *(float2*)(op+(size_t)y*Ww+x0)=v0;
            *(float2*)(op+(size_t)(y+8)*Ww+x0)=v1;
        }
    }
}

extern "C" void kernel_launch(void* const* d_in, const int* in_sizes, int n_in,
                              void* d_out, int out_size)
{
    using namespace fc;
    const float* sig =(const float*)d_in[0];
    const float* wgt =(const float*)d_in[1];
    const float* bias=(const float*)d_in[2];
    float* out=(float*)d_out;

    cudaFuncSetAttribute(k2_fwd,  cudaFuncAttributeMaxDynamicSharedMemorySize, 219648);
    cudaFuncSetAttribute(k4_gemm1,cudaFuncAttributeMaxDynamicSharedMemorySize, 89088);
    cudaFuncSetAttribute(k6_gemm2,cudaFuncAttributeMaxDynamicSharedMemorySize, 133120);

    k1_DS<<<320, 132>>>();
    k3_B1<<<dim3(Oc, Cc), 160>>>(wgt);
    k5_B2<<<dim3(19, 256), 24>>>();
    k2_fwd<<<dim3(3, Cc, Bn), 512, 219648>>>(sig);
    k2b_A<<<dim3(Cc, Fb, Bn), 288>>>();
    k4_gemm1<<<dim3(Bn, Fb, 2), 512, 89088>>>();
    k6_gemm2<<<dim3(Oc, Bn, 2), 512, 133120>>>(bias, out);
}